// round 1
// baseline (speedup 1.0000x reference)
#include <cuda_runtime.h>
#include <math.h>

#define BB 128
#define TT 48
#define DD 512
#define MM 64
#define NC 2000

// ---------------- scratch (static device memory; no allocations) --------------
struct Scratch {
  float w[TT*BB*MM];          // (t,b,m) softmax addressing
  float kproj[TT*BB*DD];      // W_f[:,d:] k + b_f
  float eaproj[TT*BB*2*DD];   // [W_e yp + b_e | W_add yp + b_add]
  float Aea[2*DD*DD];         // [W_e W_a1 ; W_add W_a1]  (1024 x 512)
  float yp[TT*BB*DD];         // W_a[:,d:] y + b_a
  float WaT[DD*DD];           // W_a[:, :d] transposed -> (j,k)
  float mem[BB*MM*DD];
  float rd[BB*DD];            // current read vector
  float f[TT*BB*DD];          // (t,b,d)
  float ea[BB*2*DD];          // current [e|a]
  float xproj[TT*BB*4*DD];    // W_ih f + b_ih + b_hh
  float H[(TT+1)*BB*DD];
  float C[(TT+1)*BB*DD];
  float bihh[4*DD];
  unsigned long long sig[BB*TT*2];
  int src[TT*BB];
  int qidx[TT*BB];
  int xidx[TT*BB];
};
__device__ Scratch gS;

__device__ __forceinline__ float sigm(float x){ return 1.f/(1.f+expf(-x)); }

// ---------------- init kernels ----------------
__global__ void init_mem_k(const float* __restrict__ Mv0){
  int i = blockIdx.x*blockDim.x + threadIdx.x;
  if (i < BB*MM*DD) gS.mem[i] = Mv0[i % (MM*DD)];
}
__global__ void init_hc_k(const float* __restrict__ hx0, const float* __restrict__ cx0){
  int i = blockIdx.x*blockDim.x + threadIdx.x;
  if (i < BB*DD){ gS.H[i] = hx0[i % DD]; gS.C[i] = cx0[i % DD]; }
}
__global__ void init_idx_k(const int* __restrict__ q, const int* __restrict__ r){
  int row = blockIdx.x*blockDim.x + threadIdx.x;
  if (row < TT*BB){
    int t = row / BB, b = row % BB;
    int qi = q[b*TT + t];
    int ri = r[b*TT + t];
    gS.qidx[row] = qi;
    gS.xidx[row] = qi + NC*ri;
  }
}
__global__ void init_bias_k(const float* __restrict__ bih, const float* __restrict__ bhh){
  int i = blockIdx.x*blockDim.x + threadIdx.x;
  if (i < 4*DD) gS.bihh[i] = bih[i] + bhh[i];
}
__global__ void transpose_wa_k(const float* __restrict__ Wa){ // Wa (512 x 1024), take first 512 cols
  int i = blockIdx.x*blockDim.x + threadIdx.x;
  if (i < DD*DD){ int j = i / DD, k = i % DD; gS.WaT[i] = Wa[k*(2*DD) + j]; }
}

// ---------------- addressing: softmax + membership signatures ----------------
__global__ void addr_kernel(const int* __restrict__ q, const float* __restrict__ Mk,
                            const float* __restrict__ k_table){
  int bt = blockIdx.x;           // b*T + t
  int b = bt / TT, t = bt % TT;
  int tid = threadIdx.x;         // 64 threads
  __shared__ float kv[DD];
  __shared__ float lg[MM];
  __shared__ float eg[MM];
  __shared__ unsigned char ivb[MM];
  int qi = q[b*TT + t];
  const float* kr = k_table + (long)qi*DD;
  for (int j = tid; j < DD; j += 64) kv[j] = kr[j];
  __syncthreads();
  const float* mkr = Mk + tid*DD;
  float s = 0.f;
  #pragma unroll 8
  for (int j = 0; j < DD; j++) s += kv[j]*mkr[j];
  lg[tid] = s;
  __syncthreads();
  float mx = -1e30f;
  for (int m = 0; m < MM; m++) mx = fmaxf(mx, lg[m]);
  float ex = expf(s - mx);
  eg[tid] = ex;
  __syncthreads();
  float sum = 0.f;
  for (int m = 0; m < MM; m++) sum += eg[m];
  float wv = ex / sum;
  gS.w[(long)t*BB*MM + b*MM + tid] = wv;
  // triangular membership -> identity value
  float mval = fminf((wv - 0.075f)/(0.088f - 0.075f), (1.0f - wv)/(1.0f - 0.088f));
  mval = fmaxf(mval, 0.f);
  int iv = (mval >= 0.6f) ? 2 : ((mval >= 0.1f) ? 1 : 0);
  ivb[tid] = (unsigned char)iv;
  __syncthreads();
  if (tid < 2){
    unsigned long long sg = 0ull;
    #pragma unroll
    for (int i = 0; i < 32; i++) sg |= ((unsigned long long)ivb[tid*32 + i]) << (2*i);
    gS.sig[(long)bt*2 + tid] = sg;
  }
}

// ---------------- hop-source search ----------------
__global__ void src_kernel(){
  int b = blockIdx.x;
  int tid = threadIdx.x;  // 64 threads
  __shared__ unsigned long long s0[TT], s1[TT];
  if (tid < TT){ s0[tid] = gS.sig[(long)(b*TT + tid)*2]; s1[tid] = gS.sig[(long)(b*TT + tid)*2 + 1]; }
  __syncthreads();
  if (tid < TT){
    int i = tid, sr = i - 1;
    unsigned long long a0 = s0[i], a1 = s1[i];
    for (int j = i - 1; j >= 0; j--){
      if (s0[j] == a0 && s1[j] == a1){ sr = j; break; }
    }
    gS.src[i*BB + b] = sr;
  }
}

// ---------------- generic fp32 GEMM: C = act(A @ W^T + bias + addend) --------
// K fixed at 512. W layout: (N, K) row-major with leading dim ldw.
#define ACT_NONE 0
#define ACT_TANH 1
#define ACT_EA   3

template<int BM,int BN,int BK,int TM,int TN,int ACT,bool HB,bool HA,bool HI>
__global__ __launch_bounds__(256) void gemm_k(
    const float* __restrict__ A, int lda,
    const float* __restrict__ W, int ldw,
    const float* __restrict__ bias,
    const float* __restrict__ addend, int ldadd,
    const int* __restrict__ rowidx,
    float* __restrict__ C, int ldc)
{
  constexpr int NT = (BM/TM)*(BN/TN);
  __shared__ float As[BK][BM];
  __shared__ float Ws[BK][BN];
  int tid = threadIdx.x;
  int tx = tid % (BN/TN);
  int ty = tid / (BN/TN);
  int row0 = blockIdx.x * BM;
  int col0 = blockIdx.y * BN;
  float acc[TM][TN];
  #pragma unroll
  for (int i = 0; i < TM; i++)
    #pragma unroll
    for (int j = 0; j < TN; j++) acc[i][j] = 0.f;

  for (int k0 = 0; k0 < 512; k0 += BK){
    #pragma unroll
    for (int i = tid; i < BM*BK; i += NT){
      int m = i / BK, kk = i % BK;
      long arow = HI ? (long)rowidx[row0 + m] : (long)(row0 + m);
      As[kk][m] = A[arow*lda + k0 + kk];
    }
    #pragma unroll
    for (int i = tid; i < BN*BK; i += NT){
      int n = i / BK, kk = i % BK;
      Ws[kk][n] = W[(long)(col0 + n)*ldw + k0 + kk];
    }
    __syncthreads();
    #pragma unroll
    for (int kk = 0; kk < BK; kk++){
      float a[TM], bvv[TN];
      #pragma unroll
      for (int i = 0; i < TM; i++) a[i] = As[kk][ty*TM + i];
      #pragma unroll
      for (int j = 0; j < TN; j++) bvv[j] = Ws[kk][tx*TN + j];
      #pragma unroll
      for (int i = 0; i < TM; i++)
        #pragma unroll
        for (int j = 0; j < TN; j++) acc[i][j] += a[i]*bvv[j];
    }
    __syncthreads();
  }
  #pragma unroll
  for (int i = 0; i < TM; i++){
    int rrow = row0 + ty*TM + i;
    #pragma unroll
    for (int j = 0; j < TN; j++){
      int c = col0 + tx*TN + j;
      float v = acc[i][j];
      if (HB) v += bias[c];
      if (HA) v += addend[(long)rrow*ldadd + c];
      if (ACT == ACT_TANH) v = tanhf(v);
      else if (ACT == ACT_EA) v = (c < DD) ? sigm(v) : tanhf(v);
      C[(long)rrow*ldc + c] = v;
    }
  }
}

// ---------------- initial read: read0 = w0 . Mv0 (broadcast mem0) -----------
__global__ void read0_kernel(const float* __restrict__ Mv0){
  int b = blockIdx.x;
  int tid = threadIdx.x; // 256
  __shared__ float w0s[MM];
  if (tid < MM) w0s[tid] = gS.w[b*MM + tid];
  __syncthreads();
  float acc0 = 0.f, acc1 = 0.f;
  #pragma unroll 4
  for (int m = 0; m < MM; m++){
    float wv = w0s[m];
    acc0 += wv * Mv0[m*DD + tid];
    acc1 += wv * Mv0[m*DD + 256 + tid];
  }
  gS.rd[b*DD + tid] = acc0;
  gS.rd[b*DD + 256 + tid] = acc1;
}

// ---------------- fused mem update + next read ------------------------------
__global__ void upd_read_kernel(int t){
  int b = blockIdx.x;
  int tid = threadIdx.x; // 256 threads, each handles d=tid and d=tid+256
  __shared__ float w0s[MM], w1s[MM], es[DD], asv[DD];
  if (tid < MM){
    w0s[tid] = gS.w[(long)t*BB*MM + b*MM + tid];
    w1s[tid] = gS.w[(long)(t+1)*BB*MM + b*MM + tid];
  }
  for (int j = tid; j < DD; j += 256){
    es[j]  = gS.ea[b*2*DD + j];
    asv[j] = gS.ea[b*2*DD + DD + j];
  }
  __syncthreads();
  float e0 = es[tid], e1 = es[tid+256], a0 = asv[tid], a1 = asv[tid+256];
  float* mb = gS.mem + (long)b*MM*DD;
  float acc0 = 0.f, acc1 = 0.f;
  #pragma unroll 4
  for (int m = 0; m < MM; m++){
    float w0 = w0s[m], w1 = w1s[m];
    float v0 = mb[m*DD + tid];
    float v1 = mb[m*DD + 256 + tid];
    v0 = v0*(1.f - w0*e0) + w0*a0;
    v1 = v1*(1.f - w0*e1) + w0*a1;
    mb[m*DD + tid] = v0;
    mb[m*DD + 256 + tid] = v1;
    acc0 += w1*v0;
    acc1 += w1*v1;
  }
  gS.rd[b*DD + tid] = acc0;
  gS.rd[b*DD + 256 + tid] = acc1;
}

// ---------------- fused LSTM step -------------------------------------------
// grid (B/32, 512/16), 256 threads. Computes all 4 gates for its (batch, col) tile.
__global__ __launch_bounds__(256) void lstm_step_kernel(int t, const float* __restrict__ Whh){
  __shared__ float Hs[16][32];
  __shared__ float Ws[4][16][16];
  __shared__ const float* hbase[32];
  __shared__ int ssrc[32];
  int tid = threadIdx.x;
  int tx = tid % 16;
  int ty = tid / 16;
  int b0 = blockIdx.x * 32;
  int n0 = blockIdx.y * 16;
  if (tid < 32){
    int sr = gS.src[t*BB + b0 + tid] + 1;
    ssrc[tid] = sr;
    hbase[tid] = gS.H + ((long)sr*BB + (b0 + tid))*DD;
  }
  __syncthreads();
  float acc[4][2];
  #pragma unroll
  for (int g = 0; g < 4; g++){ acc[g][0] = 0.f; acc[g][1] = 0.f; }

  for (int k0 = 0; k0 < DD; k0 += 16){
    #pragma unroll
    for (int i = tid; i < 512; i += 256){
      int m = i / 16, kk = i % 16;
      Hs[kk][m] = hbase[m][k0 + kk];
    }
    #pragma unroll
    for (int i = tid; i < 1024; i += 256){
      int g = i >> 8, rem = i & 255;
      int n = rem >> 4, kk = rem & 15;
      Ws[g][kk][n] = Whh[((long)(g*DD + n0 + n))*DD + k0 + kk];
    }
    __syncthreads();
    #pragma unroll
    for (int kk = 0; kk < 16; kk++){
      float h0 = Hs[kk][ty*2], h1 = Hs[kk][ty*2 + 1];
      #pragma unroll
      for (int g = 0; g < 4; g++){
        float wv = Ws[g][kk][tx];
        acc[g][0] += h0*wv;
        acc[g][1] += h1*wv;
      }
    }
    __syncthreads();
  }
  #pragma unroll
  for (int i = 0; i < 2; i++){
    int b = b0 + ty*2 + i;
    int n = n0 + tx;
    const float* xp = gS.xproj + ((long)t*BB + b)*(4*DD);
    float gi = acc[0][i] + xp[n];
    float gf = acc[1][i] + xp[DD + n];
    float gg = acc[2][i] + xp[2*DD + n];
    float go = acc[3][i] + xp[3*DD + n];
    float cin = gS.C[((long)ssrc[ty*2 + i + 0]*0 + (long)ssrc[b - b0]*BB + b)*DD + n];
    float c = sigm(gf)*cin + sigm(gi)*tanhf(gg);
    float h = sigm(go)*tanhf(c);
    long o = ((long)(t+1)*BB + b)*DD + n;
    gS.H[o] = h;
    gS.C[o] = c;
  }
}

// ---------------- prediction head -------------------------------------------
__global__ void head_kernel(const float* __restrict__ Wp, const float* __restrict__ bp,
                            float* __restrict__ out){
  int gw = (blockIdx.x*blockDim.x + threadIdx.x) >> 5;
  int lane = threadIdx.x & 31;
  if (gw >= BB*TT) return;
  int b = gw / TT, t = gw % TT;
  const float* h = gS.H + ((long)(t+1)*BB + b)*DD;
  float s = 0.f;
  for (int j = lane; j < DD; j += 32) s += h[j]*Wp[j];
  #pragma unroll
  for (int o = 16; o > 0; o >>= 1) s += __shfl_down_sync(0xffffffffu, s, o);
  if (lane == 0) out[b*TT + t] = sigm(s + bp[0]);
}

// ---------------- host orchestration ----------------------------------------
extern "C" void kernel_launch(void* const* d_in, const int* in_sizes, int n_in,
                              void* d_out, int out_size){
  (void)in_sizes; (void)n_in; (void)out_size;
  const int*   q     = (const int*)d_in[0];
  const int*   r     = (const int*)d_in[1];
  const float* Mk    = (const float*)d_in[2];
  const float* Mv0   = (const float*)d_in[3];
  const float* k_tab = (const float*)d_in[4];
  const float* x_tab = (const float*)d_in[5];
  const float* W_e   = (const float*)d_in[6];
  const float* b_e   = (const float*)d_in[7];
  const float* W_add = (const float*)d_in[8];
  const float* b_add = (const float*)d_in[9];
  const float* W_a   = (const float*)d_in[10];
  const float* b_a   = (const float*)d_in[11];
  const float* W_f   = (const float*)d_in[12];
  const float* b_f   = (const float*)d_in[13];
  const float* W_ih  = (const float*)d_in[14];
  const float* W_hh  = (const float*)d_in[15];
  const float* b_ih  = (const float*)d_in[16];
  const float* b_hh  = (const float*)d_in[17];
  const float* hx0   = (const float*)d_in[18];
  const float* cx0   = (const float*)d_in[19];
  const float* W_p   = (const float*)d_in[20];
  const float* b_p   = (const float*)d_in[21];
  float* out = (float*)d_out;

  Scratch* S = nullptr;
  cudaGetSymbolAddress((void**)&S, gS);

  const int ROWS = TT*BB; // 6144

  // ---- parallel setup ----
  init_mem_k<<<(BB*MM*DD + 255)/256, 256>>>(Mv0);
  init_hc_k<<<(BB*DD + 255)/256, 256>>>(hx0, cx0);
  init_idx_k<<<(ROWS + 255)/256, 256>>>(q, r);
  init_bias_k<<<(4*DD + 255)/256, 256>>>(b_ih, b_hh);
  transpose_wa_k<<<(DD*DD)/256, 256>>>(W_a);
  addr_kernel<<<BB*TT, 64>>>(q, Mk, k_tab);
  src_kernel<<<BB, 64>>>();

  // kproj = k_table[q] @ W_f[:, d:]^T + b_f   -> (T*B, 512)
  gemm_k<64,64,16,4,4,ACT_NONE,true,false,true><<<dim3(ROWS/64, DD/64), 256>>>(
      k_tab, DD, W_f + DD, 2*DD, b_f, nullptr, 0, S->qidx, S->kproj, DD);
  // yp = x_table[x] @ W_a[:, d:]^T + b_a
  gemm_k<64,64,16,4,4,ACT_NONE,true,false,true><<<dim3(ROWS/64, DD/64), 256>>>(
      x_tab, DD, W_a + DD, 2*DD, b_a, nullptr, 0, S->xidx, S->yp, DD);
  // A_e = W_e @ W_a1  (via WaT), A_a = W_add @ W_a1
  gemm_k<64,64,16,4,4,ACT_NONE,false,false,false><<<dim3(DD/64, DD/64), 256>>>(
      W_e, DD, S->WaT, DD, nullptr, nullptr, 0, nullptr, S->Aea, DD);
  gemm_k<64,64,16,4,4,ACT_NONE,false,false,false><<<dim3(DD/64, DD/64), 256>>>(
      W_add, DD, S->WaT, DD, nullptr, nullptr, 0, nullptr, S->Aea + DD*DD, DD);
  // eaproj = [W_e yp + b_e | W_add yp + b_add]
  gemm_k<64,64,16,4,4,ACT_NONE,true,false,false><<<dim3(ROWS/64, DD/64), 256>>>(
      S->yp, DD, W_e, DD, b_e, nullptr, 0, nullptr, S->eaproj, 2*DD);
  gemm_k<64,64,16,4,4,ACT_NONE,true,false,false><<<dim3(ROWS/64, DD/64), 256>>>(
      S->yp, DD, W_add, DD, b_add, nullptr, 0, nullptr, S->eaproj + DD, 2*DD);

  // ---- memory recurrence ----
  read0_kernel<<<BB, 256>>>(Mv0);
  // f_0
  gemm_k<32,32,16,2,2,ACT_TANH,false,true,false><<<dim3(BB/32, DD/32), 256>>>(
      S->rd, DD, W_f, 2*DD, nullptr, S->kproj, DD, nullptr, S->f, DD);
  for (int t = 0; t < TT - 1; t++){
    // [e|a]_t = act(Aea @ f_t + eaproj_t)
    gemm_k<32,32,16,2,2,ACT_EA,false,true,false><<<dim3(BB/32, (2*DD)/32), 256>>>(
        S->f + (long)t*BB*DD, DD, S->Aea, DD, nullptr,
        S->eaproj + (long)t*BB*2*DD, 2*DD, nullptr, S->ea, 2*DD);
    // mem update + read_{t+1}
    upd_read_kernel<<<BB, 256>>>(t);
    // f_{t+1}
    gemm_k<32,32,16,2,2,ACT_TANH,false,true,false><<<dim3(BB/32, DD/32), 256>>>(
        S->rd, DD, W_f, 2*DD, nullptr,
        S->kproj + (long)(t+1)*BB*DD, DD, nullptr, S->f + (long)(t+1)*BB*DD, DD);
  }

  // ---- LSTM phase ----
  // Xproj = f @ W_ih^T + (b_ih + b_hh)   -> (T*B, 2048)
  gemm_k<64,64,16,4,4,ACT_NONE,true,false,false><<<dim3(ROWS/64, (4*DD)/64), 256>>>(
      S->f, DD, W_ih, DD, S->bihh, nullptr, 0, nullptr, S->xproj, 4*DD);
  for (int t = 0; t < TT; t++){
    lstm_step_kernel<<<dim3(BB/32, DD/16), 256>>>(t, W_hh);
  }

  // ---- head ----
  head_kernel<<<(BB*TT*32 + 255)/256, 256>>>(W_p, b_p, out);
}

// round 3
// speedup vs baseline: 1.6291x; 1.6291x over previous
#include <cuda_runtime.h>
#include <math.h>

#define BB 128
#define TT 48
#define DD 512
#define MM 64
#define NC 2000

// ---------------- static device scratch --------------------------------------
struct Scratch {
  float w[TT*BB*MM];          // (t,b,m) softmax addressing
  float kproj[TT*BB*DD];      // k @ W_f2^T + b_f      rows (t*B+b)
  float eaproj[TT*BB*2*DD];   // y @ Bea^T + bias_ea   rows (t*B+b)
  float Aea[2*DD*DD];         // [W_e@Wa1 ; W_add@Wa1] (1024 x 512)
  float Bea[2*DD*DD];         // [W_e@Wa2 ; W_add@Wa2] (1024 x 512)
  float Sw[2*DD*DD];          // [W_e ; W_add] stacked (1024 x 512)
  float WaT[DD*DD];           // W_a[:, :d]^T  (k-major rows)
  float Wa2T[DD*DD];          // W_a[:, d:]^T
  float bias_ea[2*DD];
  float rd[BB*DD];            // current read vector
  float f[TT*BB*DD];          // rows (t*B+b)
  float ea[BB*2*DD];          // current [e|a]
  float xproj[TT*BB*4*DD];    // f @ W_ih^T + (b_ih+b_hh)
  float H[(TT+1)*BB*DD];
  float C[(TT+1)*BB*DD];
  float bihh[4*DD];
  unsigned long long sig[BB*TT*2];
  int src[TT*BB];
  int qidx[TT*BB];
  int xidx[TT*BB];
};
__device__ Scratch gS;
__device__ volatile unsigned gBarA[256];

__device__ __forceinline__ float sigm(float x){ return 1.f/(1.f+expf(-x)); }

// Grid barrier: slot-indexed counters, reset by reset_k at the start of every
// kernel_launch invocation. BOUNDED spin: if co-residency is ever violated the
// kernel completes (with wrong results) instead of hanging the container.
__device__ __forceinline__ void gbar(int slot, unsigned nb){
  __syncthreads();
  if (threadIdx.x == 0){
    __threadfence();
    unsigned prev = atomicAdd((unsigned*)(gBarA + slot), 1u);
    if (prev + 1u < nb){
      unsigned iter = 0;
      while (gBarA[slot] < nb && iter < 2000000u){ __nanosleep(64); iter++; }
    }
    __threadfence();
  }
  __syncthreads();
}

// ---------------- small init kernels ----------------------------------------
__global__ void reset_k(){ gBarA[threadIdx.x] = 0u; }

__global__ void init_hc_k(const float* __restrict__ hx0, const float* __restrict__ cx0){
  int i = blockIdx.x*blockDim.x + threadIdx.x;
  if (i < BB*DD){ gS.H[i] = hx0[i % DD]; gS.C[i] = cx0[i % DD]; }
}
__global__ void init_idx_k(const int* __restrict__ q, const int* __restrict__ r){
  int row = blockIdx.x*blockDim.x + threadIdx.x;
  if (row < TT*BB){
    int t = row / BB, b = row % BB;
    int qi = q[b*TT + t];
    int ri = r[b*TT + t];
    gS.qidx[row] = qi;
    gS.xidx[row] = qi + NC*ri;
  }
}
__global__ void init_bias_k(const float* __restrict__ bih, const float* __restrict__ bhh){
  int i = blockIdx.x*blockDim.x + threadIdx.x;
  if (i < 4*DD) gS.bihh[i] = bih[i] + bhh[i];
}
__global__ void trans_k(const float* __restrict__ Wa){
  int i = blockIdx.x*blockDim.x + threadIdx.x;
  if (i < DD*DD){
    int j = i / DD, k = i % DD;
    gS.WaT[i]  = Wa[(long)k*(2*DD) + j];
    gS.Wa2T[i] = Wa[(long)k*(2*DD) + DD + j];
  }
}
__global__ void stack_k(const float* __restrict__ We, const float* __restrict__ Wadd){
  int i = blockIdx.x*blockDim.x + threadIdx.x;
  if (i < DD*DD){ gS.Sw[i] = We[i]; gS.Sw[DD*DD + i] = Wadd[i]; }
}
// bias_ea[n] = dot(row_n, b_a) + (b_e|b_add)[n]
__global__ void biasea_k(const float* __restrict__ We, const float* __restrict__ Wadd,
                         const float* __restrict__ ba, const float* __restrict__ be,
                         const float* __restrict__ badd){
  int n = blockIdx.x*8 + (threadIdx.x >> 5);
  int lane = threadIdx.x & 31;
  if (n >= 2*DD) return;
  const float* row = (n < DD) ? (We + (long)n*DD) : (Wadd + (long)(n-DD)*DD);
  float s = 0.f;
  for (int k = lane; k < DD; k += 32) s += row[k]*ba[k];
  #pragma unroll
  for (int o = 16; o > 0; o >>= 1) s += __shfl_down_sync(0xffffffffu, s, o);
  if (lane == 0) gS.bias_ea[n] = s + ((n < DD) ? be[n] : badd[n-DD]);
}

// ---------------- addressing: softmax + membership signatures ----------------
__global__ void addr_kernel(const int* __restrict__ q, const float* __restrict__ Mk,
                            const float* __restrict__ k_table){
  int bt = blockIdx.x;           // b*T + t
  int b = bt / TT, t = bt % TT;
  int tid = threadIdx.x;         // 64 threads
  __shared__ float kv[DD];
  __shared__ float lg[MM];
  __shared__ float eg[MM];
  __shared__ unsigned char ivb[MM];
  int qi = q[b*TT + t];
  const float* kr = k_table + (long)qi*DD;
  for (int j = tid; j < DD; j += 64) kv[j] = kr[j];
  __syncthreads();
  const float* mkr = Mk + tid*DD;
  float s = 0.f;
  #pragma unroll 8
  for (int j = 0; j < DD; j++) s += kv[j]*mkr[j];
  lg[tid] = s;
  __syncthreads();
  float mx = -1e30f;
  for (int m = 0; m < MM; m++) mx = fmaxf(mx, lg[m]);
  float ex = expf(s - mx);
  eg[tid] = ex;
  __syncthreads();
  float sum = 0.f;
  for (int m = 0; m < MM; m++) sum += eg[m];
  float wv = ex / sum;
  gS.w[(long)t*BB*MM + b*MM + tid] = wv;
  float mval = fminf((wv - 0.075f)/(0.088f - 0.075f), (1.0f - wv)/(1.0f - 0.088f));
  mval = fmaxf(mval, 0.f);
  int iv = (mval >= 0.6f) ? 2 : ((mval >= 0.1f) ? 1 : 0);
  ivb[tid] = (unsigned char)iv;
  __syncthreads();
  if (tid < 2){
    unsigned long long sg = 0ull;
    #pragma unroll
    for (int i = 0; i < 32; i++) sg |= ((unsigned long long)ivb[tid*32 + i]) << (2*i);
    gS.sig[(long)bt*2 + tid] = sg;
  }
}

__global__ void src_kernel(){
  int b = blockIdx.x;
  int tid = threadIdx.x;  // 64 threads
  __shared__ unsigned long long s0[TT], s1[TT];
  if (tid < TT){ s0[tid] = gS.sig[(long)(b*TT + tid)*2]; s1[tid] = gS.sig[(long)(b*TT + tid)*2 + 1]; }
  __syncthreads();
  if (tid < TT){
    int i = tid, sr = i - 1;
    unsigned long long a0 = s0[i], a1 = s1[i];
    for (int j = i - 1; j >= 0; j--){
      if (s0[j] == a0 && s1[j] == a1){ sr = j; break; }
    }
    gS.src[i*BB + b] = sr;
  }
}

// ---------------- 128x128x8 SGEMM: C = A@W^T + bias -------------------------
template<bool HI, bool HB>
__global__ __launch_bounds__(256) void sgemm_k(
    const float* __restrict__ A, const int* __restrict__ rowidx,
    const float* __restrict__ W, int ldw,
    const float* __restrict__ bias, float* __restrict__ C, int ldc)
{
  __shared__ float As[8][128];
  __shared__ float Bs[8][128];
  int tid = threadIdx.x;
  int m0 = blockIdx.x * 128, n0 = blockIdx.y * 128;
  int tx = tid & 15, ty = tid >> 4;
  int lr = tid >> 1;            // 0..127
  int lk = (tid & 1) * 4;       // 0 or 4
  long arow = HI ? (long)rowidx[m0 + lr] : (long)(m0 + lr);
  const float4* Ap = (const float4*)(A + arow*DD + lk);
  const float4* Wp = (const float4*)(W + (long)(n0 + lr)*ldw + lk);

  float acc[8][8];
  #pragma unroll
  for (int i = 0; i < 8; i++)
    #pragma unroll
    for (int j = 0; j < 8; j++) acc[i][j] = 0.f;

  for (int kb = 0; kb < 64; kb++){
    float4 av = Ap[kb*2];
    float4 bv = Wp[kb*2];
    As[lk+0][lr] = av.x; As[lk+1][lr] = av.y; As[lk+2][lr] = av.z; As[lk+3][lr] = av.w;
    Bs[lk+0][lr] = bv.x; Bs[lk+1][lr] = bv.y; Bs[lk+2][lr] = bv.z; Bs[lk+3][lr] = bv.w;
    __syncthreads();
    #pragma unroll
    for (int k = 0; k < 8; k++){
      float ar[8], br[8];
      *(float4*)(ar)   = *(const float4*)&As[k][ty*8];
      *(float4*)(ar+4) = *(const float4*)&As[k][ty*8+4];
      *(float4*)(br)   = *(const float4*)&Bs[k][tx*8];
      *(float4*)(br+4) = *(const float4*)&Bs[k][tx*8+4];
      #pragma unroll
      for (int i = 0; i < 8; i++)
        #pragma unroll
        for (int j = 0; j < 8; j++) acc[i][j] += ar[i]*br[j];
    }
    __syncthreads();
  }
  #pragma unroll
  for (int i = 0; i < 8; i++){
    long m = m0 + ty*8 + i;
    #pragma unroll
    for (int j4 = 0; j4 < 8; j4 += 4){
      int n = n0 + tx*8 + j4;
      float4 o;
      o.x = acc[i][j4+0] + (HB ? bias[n+0] : 0.f);
      o.y = acc[i][j4+1] + (HB ? bias[n+1] : 0.f);
      o.z = acc[i][j4+2] + (HB ? bias[n+2] : 0.f);
      o.w = acc[i][j4+3] + (HB ? bias[n+3] : 0.f);
      *(float4*)(C + m*ldc + n) = o;
    }
  }
}

// ---------------- persistent memory recurrence ------------------------------
// grid 128 x 512 threads. Block b keeps mem[b] (64x512) resident in SMEM.
#define MEMREC_SMEM ((MM*DD + 16*516 + 128)*4)

__global__ __launch_bounds__(512) void memrec_kernel(
    const float* __restrict__ Mv0, const float* __restrict__ W_f)
{
  extern __shared__ float sm[];
  float* mem_s = sm;                 // 64*512
  float* tile  = sm + MM*DD;         // 16*516 (padded rows)
  float* w0s   = tile + 16*516;      // 64
  float* w1s   = w0s + 64;           // 64
  int bid = blockIdx.x, tid = threadIdx.x;
  int bq = bid >> 4, cq = bid & 15;
  int b0 = bq * 16;
  int myb = bid;

  // init mem from Mv0
  {
    const float4* s4 = (const float4*)Mv0;
    float4* d4 = (float4*)mem_s;
    #pragma unroll 4
    for (int i = tid; i < MM*DD/4; i += 512) d4[i] = s4[i];
  }
  if (tid < MM) w0s[tid] = gS.w[myb*MM + tid];
  __syncthreads();
  // read0
  {
    int d = tid;
    float acc = 0.f;
    #pragma unroll 8
    for (int m = 0; m < MM; m++) acc += w0s[m]*mem_s[m*DD + d];
    gS.rd[myb*DD + d] = acc;
  }
  int slot = 0;
  gbar(slot++, 128);

  for (int t = 0; t < TT; t++){
    // ---- stage1: f_t = tanh(Wf1 @ rd + kproj_t) ----
    {
      for (int i = tid; i < 16*DD/4; i += 512){
        int rr = i >> 7, k4 = i & 127;
        *(float4*)(tile + rr*516 + k4*4) = *(const float4*)(gS.rd + (b0+rr)*DD + k4*4);
      }
      __syncthreads();
      int bl = tid & 15, cl = tid >> 4;
      int c = cq*32 + cl;
      const float4* wr = (const float4*)(W_f + (long)c*(2*DD));
      const float4* rv4 = (const float4*)(tile + bl*516);
      float acc = 0.f;
      #pragma unroll 8
      for (int k4 = 0; k4 < 128; k4++){
        float4 wv = wr[k4]; float4 rv = rv4[k4];
        acc += wv.x*rv.x + wv.y*rv.y + wv.z*rv.z + wv.w*rv.w;
      }
      int brow = b0 + bl;
      acc += gS.kproj[((long)t*BB + brow)*DD + c];
      gS.f[((long)t*BB + brow)*DD + c] = tanhf(acc);
    }
    __syncthreads();
    gbar(slot++, 128);
    if (t == TT-1) break;

    // ---- stage2: [e|a]_t = act(Aea @ f_t + eaproj_t) ----
    {
      for (int i = tid; i < 16*DD/4; i += 512){
        int rr = i >> 7, k4 = i & 127;
        *(float4*)(tile + rr*516 + k4*4) =
            *(const float4*)(gS.f + ((long)t*BB + b0 + rr)*DD + k4*4);
      }
      __syncthreads();
      int bl = tid & 15, cp = tid >> 4;
      int c0 = cq*64 + cp*2;
      const float4* a0 = (const float4*)(gS.Aea + (long)c0*DD);
      const float4* a1 = (const float4*)(gS.Aea + (long)(c0+1)*DD);
      const float4* fv4 = (const float4*)(tile + bl*516);
      float acc0 = 0.f, acc1 = 0.f;
      #pragma unroll 8
      for (int k4 = 0; k4 < 128; k4++){
        float4 fv = fv4[k4];
        float4 w0v = a0[k4], w1v = a1[k4];
        acc0 += w0v.x*fv.x + w0v.y*fv.y + w0v.z*fv.z + w0v.w*fv.w;
        acc1 += w1v.x*fv.x + w1v.y*fv.y + w1v.z*fv.z + w1v.w*fv.w;
      }
      int brow = b0 + bl;
      const float* ep = gS.eaproj + ((long)t*BB + brow)*(2*DD);
      float v0 = acc0 + ep[c0];
      float v1 = acc1 + ep[c0+1];
      float* eo = gS.ea + brow*(2*DD);
      if (cq < 8){ eo[c0] = sigm(v0); eo[c0+1] = sigm(v1); }
      else       { eo[c0] = tanhf(v0); eo[c0+1] = tanhf(v1); }
    }
    __syncthreads();
    gbar(slot++, 128);

    // ---- stage3: mem update (SMEM-resident) + rd_{t+1} ----
    {
      if (tid < MM){
        w0s[tid] = gS.w[((long)t*BB + myb)*MM + tid];
        w1s[tid] = gS.w[((long)(t+1)*BB + myb)*MM + tid];
      }
      __syncthreads();
      int d = tid;
      float ev = gS.ea[myb*(2*DD) + d];
      float av = gS.ea[myb*(2*DD) + DD + d];
      float acc = 0.f;
      #pragma unroll 8
      for (int m = 0; m < MM; m++){
        float v = mem_s[m*DD + d];
        v = v*(1.f - w0s[m]*ev) + w0s[m]*av;
        mem_s[m*DD + d] = v;
        acc += w1s[m]*v;
      }
      gS.rd[myb*DD + d] = acc;
    }
    gbar(slot++, 128);
  }
}

// ---------------- persistent hop-LSTM ---------------------------------------
#define LSTM_SMEM ((64*516 + 32*512)*4 + 128)
#define LSTM_SLOT0 160

__global__ __launch_bounds__(256) void lstm_kernel(const float* __restrict__ Whh){
  extern __shared__ float sm[];
  float* Ws = sm;                        // 64 rows x 516 (padded)
  float* Hs = sm + 64*516;               // 32 x 512
  int* ssrc = (int*)(Hs + 32*512);       // 32
  int bid = blockIdx.x, tid = threadIdx.x;
  int n0 = (bid & 31) * 16;
  int b0 = (bid >> 5) * 32;

  // cache W_hh tile once
  {
    float4* WsV = (float4*)Ws;
    for (int i = tid; i < 64*128; i += 256){
      int r = i >> 7, k4 = i & 127;
      int g = r >> 4, n = r & 15;
      WsV[(long)r*129 + k4] =
          ((const float4*)(Whh + ((long)(g*DD + n0 + n))*DD))[k4];
    }
  }
  __syncthreads();

  int n_local = tid & 15;
  int bg = tid >> 4;
  const float4* WsV = (const float4*)Ws;
  float4* HsV = (float4*)Hs;

  for (int t = 0; t < TT; t++){
    if (tid < 32) ssrc[tid] = gS.src[t*BB + b0 + tid];
    __syncthreads();
    for (int i = tid; i < 32*128; i += 256){
      int row = i >> 7, k4 = i & 127;
      long hrow = ((long)(ssrc[row]+1)*BB + (b0 + row))*DD;
      HsV[row*128 + k4] = ((const float4*)(gS.H + hrow))[k4];
    }
    __syncthreads();

    float acc[2][4];
    #pragma unroll
    for (int bi = 0; bi < 2; bi++)
      #pragma unroll
      for (int g = 0; g < 4; g++) acc[bi][g] = 0.f;

    #pragma unroll 2
    for (int k4 = 0; k4 < 128; k4++){
      float4 h0 = HsV[(bg*2+0)*128 + k4];
      float4 h1 = HsV[(bg*2+1)*128 + k4];
      #pragma unroll
      for (int g = 0; g < 4; g++){
        float4 wv = WsV[(long)(g*16 + n_local)*129 + k4];
        acc[0][g] += wv.x*h0.x + wv.y*h0.y + wv.z*h0.z + wv.w*h0.w;
        acc[1][g] += wv.x*h1.x + wv.y*h1.y + wv.z*h1.z + wv.w*h1.w;
      }
    }

    #pragma unroll
    for (int bi = 0; bi < 2; bi++){
      int bl = bg*2 + bi;
      int b = b0 + bl;
      int srcp = ssrc[bl] + 1;
      int n = n0 + n_local;
      const float* xp = gS.xproj + ((long)t*BB + b)*(4*DD);
      float gi = acc[bi][0] + xp[n];
      float gf = acc[bi][1] + xp[DD + n];
      float gg = acc[bi][2] + xp[2*DD + n];
      float go = acc[bi][3] + xp[3*DD + n];
      float cin = gS.C[((long)srcp*BB + b)*DD + n];
      float c = sigm(gf)*cin + sigm(gi)*tanhf(gg);
      float h = sigm(go)*tanhf(c);
      long o = ((long)(t+1)*BB + b)*DD + n;
      gS.H[o] = h;
      gS.C[o] = c;
    }
    __syncthreads();
    gbar(LSTM_SLOT0 + t, 128);
  }
}

// ---------------- prediction head -------------------------------------------
__global__ void head_kernel(const float* __restrict__ Wp, const float* __restrict__ bp,
                            float* __restrict__ out){
  int gw = (blockIdx.x*blockDim.x + threadIdx.x) >> 5;
  int lane = threadIdx.x & 31;
  if (gw >= BB*TT) return;
  int b = gw / TT, t = gw % TT;
  const float* h = gS.H + ((long)(t+1)*BB + b)*DD;
  float s = 0.f;
  for (int j = lane; j < DD; j += 32) s += h[j]*Wp[j];
  #pragma unroll
  for (int o = 16; o > 0; o >>= 1) s += __shfl_down_sync(0xffffffffu, s, o);
  if (lane == 0) out[b*TT + t] = sigm(s + bp[0]);
}

// ---------------- host orchestration ----------------------------------------
extern "C" void kernel_launch(void* const* d_in, const int* in_sizes, int n_in,
                              void* d_out, int out_size){
  (void)in_sizes; (void)n_in; (void)out_size;
  const int*   q     = (const int*)d_in[0];
  const int*   r     = (const int*)d_in[1];
  const float* Mk    = (const float*)d_in[2];
  const float* Mv0   = (const float*)d_in[3];
  const float* k_tab = (const float*)d_in[4];
  const float* x_tab = (const float*)d_in[5];
  const float* W_e   = (const float*)d_in[6];
  const float* b_e   = (const float*)d_in[7];
  const float* W_add = (const float*)d_in[8];
  const float* b_add = (const float*)d_in[9];
  const float* W_a   = (const float*)d_in[10];
  const float* b_a   = (const float*)d_in[11];
  const float* W_f   = (const float*)d_in[12];
  const float* b_f   = (const float*)d_in[13];
  const float* W_ih  = (const float*)d_in[14];
  const float* W_hh  = (const float*)d_in[15];
  const float* b_ih  = (const float*)d_in[16];
  const float* b_hh  = (const float*)d_in[17];
  const float* hx0   = (const float*)d_in[18];
  const float* cx0   = (const float*)d_in[19];
  const float* W_p   = (const float*)d_in[20];
  const float* b_p   = (const float*)d_in[21];
  float* out = (float*)d_out;

  Scratch* S = nullptr;
  cudaGetSymbolAddress((void**)&S, gS);

  cudaFuncSetAttribute(memrec_kernel, cudaFuncAttributeMaxDynamicSharedMemorySize, MEMREC_SMEM);
  cudaFuncSetAttribute(lstm_kernel,   cudaFuncAttributeMaxDynamicSharedMemorySize, LSTM_SMEM);

  const int ROWS = TT*BB; // 6144

  // ---- parallel setup ----
  reset_k<<<1,256>>>();
  init_hc_k<<<(BB*DD + 255)/256, 256>>>(hx0, cx0);
  init_idx_k<<<(ROWS + 255)/256, 256>>>(q, r);
  init_bias_k<<<(4*DD + 255)/256, 256>>>(b_ih, b_hh);
  trans_k<<<(DD*DD + 255)/256, 256>>>(W_a);
  stack_k<<<(DD*DD + 255)/256, 256>>>(W_e, W_add);
  biasea_k<<<(2*DD)/8, 256>>>(W_e, W_add, b_a, b_e, b_add);
  addr_kernel<<<BB*TT, 64>>>(q, Mk, k_tab);
  src_kernel<<<BB, 64>>>();

  // Aea = Sw @ WaT^T ; Bea = Sw @ Wa2T^T        (1024 x 512 each)
  sgemm_k<false,false><<<dim3(8,4), 256>>>(S->Sw, nullptr, S->WaT, DD, nullptr, S->Aea, DD);
  sgemm_k<false,false><<<dim3(8,4), 256>>>(S->Sw, nullptr, S->Wa2T, DD, nullptr, S->Bea, DD);
  // kproj = k_table[q] @ W_f2^T + b_f           (6144 x 512)
  sgemm_k<true,true><<<dim3(48,4), 256>>>(k_tab, S->qidx, W_f + DD, 2*DD, b_f, S->kproj, DD);
  // eaproj = x_table[x] @ Bea^T + bias_ea       (6144 x 1024)
  sgemm_k<true,true><<<dim3(48,8), 256>>>(x_tab, S->xidx, S->Bea, DD, S->bias_ea, S->eaproj, 2*DD);

  // ---- persistent memory recurrence ----
  memrec_kernel<<<128, 512, MEMREC_SMEM>>>(Mv0, W_f);

  // xproj = f @ W_ih^T + (b_ih + b_hh)          (6144 x 2048)
  sgemm_k<false,true><<<dim3(48,16), 256>>>(S->f, nullptr, W_ih, DD, S->bihh, S->xproj, 4*DD);

  // ---- persistent hop-LSTM ----
  lstm_kernel<<<128, 256, LSTM_SMEM>>>(W_hh);

  // ---- head ----
  head_kernel<<<(BB*TT*32 + 255)/256, 256>>>(W_p, b_p, out);
}

// round 4
// speedup vs baseline: 1.9079x; 1.1711x over previous
#include <cuda_runtime.h>
#include <math.h>

#define BB 128
#define TT 48
#define DD 512
#define MM 64
#define NC 2000

typedef unsigned long long u64;

// ---------------- f32x2 packed helpers (sm_100+) -----------------------------
__device__ __forceinline__ u64 ffma2(u64 a, u64 b, u64 c){
  u64 d; asm("fma.rn.f32x2 %0, %1, %2, %3;" : "=l"(d) : "l"(a), "l"(b), "l"(c));
  return d;
}
__device__ __forceinline__ u64 f2pack(float lo, float hi){
  u64 r; asm("mov.b64 %0, {%1, %2};" : "=l"(r) : "f"(lo), "f"(hi)); return r;
}
__device__ __forceinline__ void f2unp(u64 v, float& lo, float& hi){
  asm("mov.b64 {%0, %1}, %2;" : "=f"(lo), "=f"(hi) : "l"(v));
}
__device__ __forceinline__ float f2sum(u64 v){
  float lo, hi; f2unp(v, lo, hi); return lo + hi;
}

// ---------------- static device scratch --------------------------------------
struct Scratch {
  float w_table[NC*MM];           // softmax addressing per q id
  unsigned long long sig_table[NC*2];
  float kproj_t[2048*DD];         // per-q: k_table @ W_f2^T + b_f
  float eaproj_t[4096*2*DD];      // per-x: x_table @ Bea^T + bias_ea
  float Aea[2*DD*DD];             // [W_e@Wa1 ; W_add@Wa1] (1024 x 512)
  float Bea[2*DD*DD];             // [W_e@Wa2 ; W_add@Wa2]
  float Sw[2*DD*DD];              // [W_e ; W_add] stacked
  float WaT[DD*DD];
  float Wa2T[DD*DD];
  float bias_ea[2*DD];
  float rd[BB*DD];
  float f[TT*BB*DD];
  float ea[BB*2*DD];
  float xproj[TT*BB*4*DD];
  float H[(TT+1)*BB*DD];
  float C[(TT+1)*BB*DD];
  float bihh[4*DD];
  int src[TT*BB];
  int qidx[TT*BB];                // layout t*BB + b
  int xidx[TT*BB];
};
__device__ Scratch gS;
__device__ volatile unsigned gBarA[256];

__device__ __forceinline__ float sigm(float x){ return 1.f/(1.f+expf(-x)); }

// Bounded-spin grid barrier (slot counters reset each invocation).
__device__ __forceinline__ void gbar(int slot, unsigned nb){
  __syncthreads();
  if (threadIdx.x == 0){
    __threadfence();
    unsigned prev = atomicAdd((unsigned*)(gBarA + slot), 1u);
    if (prev + 1u < nb){
      unsigned iter = 0;
      while (gBarA[slot] < nb && iter < 2000000u){ __nanosleep(64); iter++; }
    }
    __threadfence();
  }
  __syncthreads();
}

// ---------------- small init kernels ----------------------------------------
__global__ void reset_k(){ gBarA[threadIdx.x] = 0u; }

__global__ void init_hc_k(const float* __restrict__ hx0, const float* __restrict__ cx0){
  int i = blockIdx.x*blockDim.x + threadIdx.x;
  if (i < BB*DD){ gS.H[i] = hx0[i % DD]; gS.C[i] = cx0[i % DD]; }
}
__global__ void init_idx_k(const int* __restrict__ q, const int* __restrict__ r){
  int row = blockIdx.x*blockDim.x + threadIdx.x;
  if (row < TT*BB){
    int t = row / BB, b = row % BB;
    int qi = q[b*TT + t];
    int ri = r[b*TT + t];
    gS.qidx[row] = qi;
    gS.xidx[row] = qi + NC*ri;
  }
}
__global__ void init_bias_k(const float* __restrict__ bih, const float* __restrict__ bhh){
  int i = blockIdx.x*blockDim.x + threadIdx.x;
  if (i < 4*DD) gS.bihh[i] = bih[i] + bhh[i];
}
__global__ void trans_k(const float* __restrict__ Wa){
  int i = blockIdx.x*blockDim.x + threadIdx.x;
  if (i < DD*DD){
    int j = i / DD, k = i % DD;
    gS.WaT[i]  = Wa[(long)k*(2*DD) + j];
    gS.Wa2T[i] = Wa[(long)k*(2*DD) + DD + j];
  }
}
__global__ void stack_k(const float* __restrict__ We, const float* __restrict__ Wadd){
  int i = blockIdx.x*blockDim.x + threadIdx.x;
  if (i < DD*DD){ gS.Sw[i] = We[i]; gS.Sw[DD*DD + i] = Wadd[i]; }
}
__global__ void biasea_k(const float* __restrict__ We, const float* __restrict__ Wadd,
                         const float* __restrict__ ba, const float* __restrict__ be,
                         const float* __restrict__ badd){
  int n = blockIdx.x*8 + (threadIdx.x >> 5);
  int lane = threadIdx.x & 31;
  if (n >= 2*DD) return;
  const float* row = (n < DD) ? (We + (long)n*DD) : (Wadd + (long)(n-DD)*DD);
  float s = 0.f;
  for (int k = lane; k < DD; k += 32) s += row[k]*ba[k];
  #pragma unroll
  for (int o = 16; o > 0; o >>= 1) s += __shfl_down_sync(0xffffffffu, s, o);
  if (lane == 0) gS.bias_ea[n] = s + ((n < DD) ? be[n] : badd[n-DD]);
}

// ---------------- addressing per q id: softmax + signature -------------------
__global__ void addr_kernel(const float* __restrict__ Mk,
                            const float* __restrict__ k_table){
  int id = blockIdx.x;           // 0..NC-1
  int tid = threadIdx.x;         // 64 threads
  __shared__ float kv[DD];
  __shared__ float lg[MM];
  __shared__ float eg[MM];
  __shared__ unsigned char ivb[MM];
  const float* kr = k_table + (long)id*DD;
  for (int j = tid; j < DD; j += 64) kv[j] = kr[j];
  __syncthreads();
  const ulonglong2* mk2 = (const ulonglong2*)(Mk + (long)tid*DD);
  const ulonglong2* kv2 = (const ulonglong2*)kv;
  u64 acc2 = 0;
  #pragma unroll 8
  for (int k4 = 0; k4 < 128; k4++){
    ulonglong2 m2 = mk2[k4], k2 = kv2[k4];
    acc2 = ffma2(m2.x, k2.x, acc2);
    acc2 = ffma2(m2.y, k2.y, acc2);
  }
  float s = f2sum(acc2);
  lg[tid] = s;
  __syncthreads();
  float mx = -1e30f;
  for (int m = 0; m < MM; m++) mx = fmaxf(mx, lg[m]);
  float ex = expf(s - mx);
  eg[tid] = ex;
  __syncthreads();
  float sum = 0.f;
  for (int m = 0; m < MM; m++) sum += eg[m];
  float wv = ex / sum;
  gS.w_table[(long)id*MM + tid] = wv;
  float mval = fminf((wv - 0.075f)/(0.088f - 0.075f), (1.0f - wv)/(1.0f - 0.088f));
  mval = fmaxf(mval, 0.f);
  int iv = (mval >= 0.6f) ? 2 : ((mval >= 0.1f) ? 1 : 0);
  ivb[tid] = (unsigned char)iv;
  __syncthreads();
  if (tid < 2){
    unsigned long long sg = 0ull;
    #pragma unroll
    for (int i = 0; i < 32; i++) sg |= ((unsigned long long)ivb[tid*32 + i]) << (2*i);
    gS.sig_table[(long)id*2 + tid] = sg;
  }
}

__global__ void src_kernel(){
  int b = blockIdx.x;
  int tid = threadIdx.x;  // 64 threads
  __shared__ unsigned long long s0[TT], s1[TT];
  if (tid < TT){
    int id = gS.qidx[tid*BB + b];
    s0[tid] = gS.sig_table[(long)id*2];
    s1[tid] = gS.sig_table[(long)id*2 + 1];
  }
  __syncthreads();
  if (tid < TT){
    int i = tid, sr = i - 1;
    unsigned long long a0 = s0[i], a1 = s1[i];
    for (int j = i - 1; j >= 0; j--){
      if (s0[j] == a0 && s1[j] == a1){ sr = j; break; }
    }
    gS.src[i*BB + b] = sr;
  }
}

// ---------------- 128x128x8 SGEMM via f32x2: C = A@W^T + bias ---------------
// A: Mrows x 512 (lda=512). W: (N, K=512) row-major ldw. Row-guarded stores.
template<bool HB>
__global__ __launch_bounds__(256) void sgemm2_k(
    const float* __restrict__ A, int Mrows,
    const float* __restrict__ W, int ldw,
    const float* __restrict__ bias,
    float* __restrict__ C, int ldc)
{
  __shared__ u64 As2[8][128];    // duplicated pairs (a,a)
  __shared__ float Bs[8][128];
  int tid = threadIdx.x;
  int m0 = blockIdx.x * 128, n0 = blockIdx.y * 128;
  int tx = tid & 15, ty = tid >> 4;
  int lr = tid >> 1;
  int lk = (tid & 1) * 4;
  int mrow = m0 + lr;
  int mload = mrow < Mrows ? mrow : (Mrows - 1);
  const float4* Ap = (const float4*)(A + (long)mload*DD + lk);
  const float4* Wp = (const float4*)(W + (long)(n0 + lr)*ldw + lk);

  u64 acc2[8][4];
  #pragma unroll
  for (int i = 0; i < 8; i++)
    #pragma unroll
    for (int j = 0; j < 4; j++) acc2[i][j] = 0ull;

  for (int kb = 0; kb < 64; kb++){
    float4 av = Ap[kb*2];
    float4 bv = Wp[kb*2];
    As2[lk+0][lr] = f2pack(av.x, av.x);
    As2[lk+1][lr] = f2pack(av.y, av.y);
    As2[lk+2][lr] = f2pack(av.z, av.z);
    As2[lk+3][lr] = f2pack(av.w, av.w);
    Bs[lk+0][lr] = bv.x; Bs[lk+1][lr] = bv.y; Bs[lk+2][lr] = bv.z; Bs[lk+3][lr] = bv.w;
    __syncthreads();
    #pragma unroll
    for (int k = 0; k < 8; k++){
      const ulonglong2* a4 = (const ulonglong2*)&As2[k][ty*8];
      ulonglong2 t0 = a4[0], t1 = a4[1], t2 = a4[2], t3 = a4[3];
      u64 a2[8] = {t0.x, t0.y, t1.x, t1.y, t2.x, t2.y, t3.x, t3.y};
      float4 bl = *(const float4*)&Bs[k][tx*8];
      float4 bh = *(const float4*)&Bs[k][tx*8+4];
      u64 b2[4] = {f2pack(bl.x, bl.y), f2pack(bl.z, bl.w),
                   f2pack(bh.x, bh.y), f2pack(bh.z, bh.w)};
      #pragma unroll
      for (int i = 0; i < 8; i++)
        #pragma unroll
        for (int j = 0; j < 4; j++) acc2[i][j] = ffma2(a2[i], b2[j], acc2[i][j]);
    }
    __syncthreads();
  }
  #pragma unroll
  for (int i = 0; i < 8; i++){
    int m = m0 + ty*8 + i;
    if (m < Mrows){
      int n = n0 + tx*8;
      float c0,c1,c2,c3,c4,c5,c6,c7;
      f2unp(acc2[i][0], c0, c1); f2unp(acc2[i][1], c2, c3);
      f2unp(acc2[i][2], c4, c5); f2unp(acc2[i][3], c6, c7);
      float4 o0, o1;
      o0.x = c0 + (HB ? bias[n+0] : 0.f);
      o0.y = c1 + (HB ? bias[n+1] : 0.f);
      o0.z = c2 + (HB ? bias[n+2] : 0.f);
      o0.w = c3 + (HB ? bias[n+3] : 0.f);
      o1.x = c4 + (HB ? bias[n+4] : 0.f);
      o1.y = c5 + (HB ? bias[n+5] : 0.f);
      o1.z = c6 + (HB ? bias[n+6] : 0.f);
      o1.w = c7 + (HB ? bias[n+7] : 0.f);
      *(float4*)(C + (long)m*ldc + n)     = o0;
      *(float4*)(C + (long)m*ldc + n + 4) = o1;
    }
  }
}

// ---------------- persistent memory recurrence ------------------------------
#define MEMREC_SMEM ((MM*DD + 16*516 + 128)*4)

__global__ __launch_bounds__(512) void memrec_kernel(
    const float* __restrict__ Mv0, const float* __restrict__ W_f)
{
  extern __shared__ float sm[];
  float* mem_s = sm;                 // 64*512
  float* tile  = sm + MM*DD;         // 16*516 (padded rows)
  float* w0s   = tile + 16*516;      // 64
  float* w1s   = w0s + 64;           // 64
  int bid = blockIdx.x, tid = threadIdx.x;
  int bq = bid >> 4, cq = bid & 15;
  int b0 = bq * 16;
  int myb = bid;

  {
    const float4* s4 = (const float4*)Mv0;
    float4* d4 = (float4*)mem_s;
    #pragma unroll 4
    for (int i = tid; i < MM*DD/4; i += 512) d4[i] = s4[i];
  }
  if (tid < MM){
    int qid = gS.qidx[myb];   // t = 0
    w0s[tid] = gS.w_table[(long)qid*MM + tid];
  }
  __syncthreads();
  {
    int d = tid;
    float acc = 0.f;
    #pragma unroll 8
    for (int m = 0; m < MM; m++) acc += w0s[m]*mem_s[m*DD + d];
    gS.rd[myb*DD + d] = acc;
  }
  int slot = 0;
  gbar(slot++, 128);

  for (int t = 0; t < TT; t++){
    // ---- stage1: f_t = tanh(Wf1 @ rd + kproj_table[q]) ----
    {
      for (int i = tid; i < 16*DD/4; i += 512){
        int rr = i >> 7, k4 = i & 127;
        *(float4*)(tile + rr*516 + k4*4) = *(const float4*)(gS.rd + (b0+rr)*DD + k4*4);
      }
      __syncthreads();
      int bl = tid & 15, cl = tid >> 4;
      int c = cq*32 + cl;
      const ulonglong2* wr2 = (const ulonglong2*)(W_f + (long)c*(2*DD));
      const ulonglong2* rv2 = (const ulonglong2*)(tile + bl*516);
      u64 acc2 = 0;
      #pragma unroll 8
      for (int k4 = 0; k4 < 128; k4++){
        ulonglong2 wv = wr2[k4], rv = rv2[k4];
        acc2 = ffma2(wv.x, rv.x, acc2);
        acc2 = ffma2(wv.y, rv.y, acc2);
      }
      int brow = b0 + bl;
      int qid = gS.qidx[t*BB + brow];
      float acc = f2sum(acc2) + gS.kproj_t[(long)qid*DD + c];
      gS.f[((long)t*BB + brow)*DD + c] = tanhf(acc);
    }
    __syncthreads();
    gbar(slot++, 128);
    if (t == TT-1) break;

    // ---- stage2: [e|a]_t = act(Aea @ f_t + eaproj_table[x]) ----
    {
      for (int i = tid; i < 16*DD/4; i += 512){
        int rr = i >> 7, k4 = i & 127;
        *(float4*)(tile + rr*516 + k4*4) =
            *(const float4*)(gS.f + ((long)t*BB + b0 + rr)*DD + k4*4);
      }
      __syncthreads();
      int bl = tid & 15, cp = tid >> 4;
      int c0 = cq*64 + cp*2;
      const ulonglong2* a0 = (const ulonglong2*)(gS.Aea + (long)c0*DD);
      const ulonglong2* a1 = (const ulonglong2*)(gS.Aea + (long)(c0+1)*DD);
      const ulonglong2* fv2 = (const ulonglong2*)(tile + bl*516);
      u64 acc0_2 = 0, acc1_2 = 0;
      #pragma unroll 8
      for (int k4 = 0; k4 < 128; k4++){
        ulonglong2 fv = fv2[k4];
        ulonglong2 w0v = a0[k4], w1v = a1[k4];
        acc0_2 = ffma2(w0v.x, fv.x, acc0_2);
        acc0_2 = ffma2(w0v.y, fv.y, acc0_2);
        acc1_2 = ffma2(w1v.x, fv.x, acc1_2);
        acc1_2 = ffma2(w1v.y, fv.y, acc1_2);
      }
      int brow = b0 + bl;
      int xid = gS.xidx[t*BB + brow];
      const float* ep = gS.eaproj_t + (long)xid*(2*DD);
      float v0 = f2sum(acc0_2) + ep[c0];
      float v1 = f2sum(acc1_2) + ep[c0+1];
      float* eo = gS.ea + brow*(2*DD);
      if (cq < 8){ eo[c0] = sigm(v0); eo[c0+1] = sigm(v1); }
      else       { eo[c0] = tanhf(v0); eo[c0+1] = tanhf(v1); }
    }
    __syncthreads();
    gbar(slot++, 128);

    // ---- stage3: mem update (SMEM-resident) + rd_{t+1} ----
    {
      if (tid < MM){
        int q0 = gS.qidx[t*BB + myb];
        int q1 = gS.qidx[(t+1)*BB + myb];
        w0s[tid] = gS.w_table[(long)q0*MM + tid];
        w1s[tid] = gS.w_table[(long)q1*MM + tid];
      }
      __syncthreads();
      int d = tid;
      float ev = gS.ea[myb*(2*DD) + d];
      float av = gS.ea[myb*(2*DD) + DD + d];
      float acc = 0.f;
      #pragma unroll 8
      for (int m = 0; m < MM; m++){
        float v = mem_s[m*DD + d];
        v = v*(1.f - w0s[m]*ev) + w0s[m]*av;
        mem_s[m*DD + d] = v;
        acc += w1s[m]*v;
      }
      gS.rd[myb*DD + d] = acc;
    }
    gbar(slot++, 128);
  }
}

// ---------------- persistent hop-LSTM ---------------------------------------
#define LSTM_SMEM ((64*516 + 32*512)*4 + 128)
#define LSTM_SLOT0 160

__global__ __launch_bounds__(256) void lstm_kernel(const float* __restrict__ Whh){
  extern __shared__ float sm[];
  float* Ws = sm;                        // 64 rows x 516 (padded)
  float* Hs = sm + 64*516;               // 32 x 512
  int* ssrc = (int*)(Hs + 32*512);       // 32
  int bid = blockIdx.x, tid = threadIdx.x;
  int n0 = (bid & 31) * 16;
  int b0 = (bid >> 5) * 32;

  {
    float4* WsV = (float4*)Ws;
    for (int i = tid; i < 64*128; i += 256){
      int r = i >> 7, k4 = i & 127;
      int g = r >> 4, n = r & 15;
      WsV[(long)r*129 + k4] =
          ((const float4*)(Whh + ((long)(g*DD + n0 + n))*DD))[k4];
    }
  }
  __syncthreads();

  int n_local = tid & 15;
  int bg = tid >> 4;
  const ulonglong2* WsV2 = (const ulonglong2*)Ws;
  const ulonglong2* HsV2 = (const ulonglong2*)Hs;
  float4* HsV = (float4*)Hs;

  for (int t = 0; t < TT; t++){
    if (tid < 32) ssrc[tid] = gS.src[t*BB + b0 + tid];
    __syncthreads();
    for (int i = tid; i < 32*128; i += 256){
      int row = i >> 7, k4 = i & 127;
      long hrow = ((long)(ssrc[row]+1)*BB + (b0 + row))*DD;
      HsV[row*128 + k4] = ((const float4*)(gS.H + hrow))[k4];
    }
    __syncthreads();

    u64 acc2[2][4];
    #pragma unroll
    for (int bi = 0; bi < 2; bi++)
      #pragma unroll
      for (int g = 0; g < 4; g++) acc2[bi][g] = 0ull;

    #pragma unroll 2
    for (int k4 = 0; k4 < 128; k4++){
      ulonglong2 h0 = HsV2[(bg*2+0)*128 + k4];
      ulonglong2 h1 = HsV2[(bg*2+1)*128 + k4];
      #pragma unroll
      for (int g = 0; g < 4; g++){
        ulonglong2 wv = WsV2[(long)(g*16 + n_local)*129 + k4];
        acc2[0][g] = ffma2(wv.x, h0.x, acc2[0][g]);
        acc2[0][g] = ffma2(wv.y, h0.y, acc2[0][g]);
        acc2[1][g] = ffma2(wv.x, h1.x, acc2[1][g]);
        acc2[1][g] = ffma2(wv.y, h1.y, acc2[1][g]);
      }
    }

    #pragma unroll
    for (int bi = 0; bi < 2; bi++){
      int bl = bg*2 + bi;
      int b = b0 + bl;
      int srcp = ssrc[bl] + 1;
      int n = n0 + n_local;
      const float* xp = gS.xproj + ((long)t*BB + b)*(4*DD);
      float gi = f2sum(acc2[bi][0]) + xp[n];
      float gf = f2sum(acc2[bi][1]) + xp[DD + n];
      float gg = f2sum(acc2[bi][2]) + xp[2*DD + n];
      float go = f2sum(acc2[bi][3]) + xp[3*DD + n];
      float cin = gS.C[((long)srcp*BB + b)*DD + n];
      float c = sigm(gf)*cin + sigm(gi)*tanhf(gg);
      float h = sigm(go)*tanhf(c);
      long o = ((long)(t+1)*BB + b)*DD + n;
      gS.H[o] = h;
      gS.C[o] = c;
    }
    __syncthreads();
    gbar(LSTM_SLOT0 + t, 128);
  }
}

// ---------------- prediction head -------------------------------------------
__global__ void head_kernel(const float* __restrict__ Wp, const float* __restrict__ bp,
                            float* __restrict__ out){
  int gw = (blockIdx.x*blockDim.x + threadIdx.x) >> 5;
  int lane = threadIdx.x & 31;
  if (gw >= BB*TT) return;
  int b = gw / TT, t = gw % TT;
  const float* h = gS.H + ((long)(t+1)*BB + b)*DD;
  float s = 0.f;
  for (int j = lane; j < DD; j += 32) s += h[j]*Wp[j];
  #pragma unroll
  for (int o = 16; o > 0; o >>= 1) s += __shfl_down_sync(0xffffffffu, s, o);
  if (lane == 0) out[b*TT + t] = sigm(s + bp[0]);
}

// ---------------- host orchestration ----------------------------------------
extern "C" void kernel_launch(void* const* d_in, const int* in_sizes, int n_in,
                              void* d_out, int out_size){
  (void)in_sizes; (void)n_in; (void)out_size;
  const int*   q     = (const int*)d_in[0];
  const int*   r     = (const int*)d_in[1];
  const float* Mk    = (const float*)d_in[2];
  const float* Mv0   = (const float*)d_in[3];
  const float* k_tab = (const float*)d_in[4];
  const float* x_tab = (const float*)d_in[5];
  const float* W_e   = (const float*)d_in[6];
  const float* b_e   = (const float*)d_in[7];
  const float* W_add = (const float*)d_in[8];
  const float* b_add = (const float*)d_in[9];
  const float* W_a   = (const float*)d_in[10];
  const float* b_a   = (const float*)d_in[11];
  const float* W_f   = (const float*)d_in[12];
  const float* b_f   = (const float*)d_in[13];
  const float* W_ih  = (const float*)d_in[14];
  const float* W_hh  = (const float*)d_in[15];
  const float* b_ih  = (const float*)d_in[16];
  const float* b_hh  = (const float*)d_in[17];
  const float* hx0   = (const float*)d_in[18];
  const float* cx0   = (const float*)d_in[19];
  const float* W_p   = (const float*)d_in[20];
  const float* b_p   = (const float*)d_in[21];
  float* out = (float*)d_out;

  Scratch* S = nullptr;
  cudaGetSymbolAddress((void**)&S, gS);

  cudaFuncSetAttribute(memrec_kernel, cudaFuncAttributeMaxDynamicSharedMemorySize, MEMREC_SMEM);
  cudaFuncSetAttribute(lstm_kernel,   cudaFuncAttributeMaxDynamicSharedMemorySize, LSTM_SMEM);

  const int ROWS = TT*BB; // 6144

  // ---- parallel setup ----
  reset_k<<<1,256>>>();
  init_hc_k<<<(BB*DD + 255)/256, 256>>>(hx0, cx0);
  init_idx_k<<<(ROWS + 255)/256, 256>>>(q, r);
  init_bias_k<<<(4*DD + 255)/256, 256>>>(b_ih, b_hh);
  trans_k<<<(DD*DD + 255)/256, 256>>>(W_a);
  stack_k<<<(DD*DD + 255)/256, 256>>>(W_e, W_add);
  biasea_k<<<(2*DD)/8, 256>>>(W_e, W_add, b_a, b_e, b_add);
  addr_kernel<<<NC, 64>>>(Mk, k_tab);
  src_kernel<<<BB, 64>>>();

  // Aea = Sw @ WaT^T ; Bea = Sw @ Wa2T^T        (1024 x 512 each)
  sgemm2_k<false><<<dim3(8,4), 256>>>(S->Sw, 1024, S->WaT, DD, nullptr, S->Aea, DD);
  sgemm2_k<false><<<dim3(8,4), 256>>>(S->Sw, 1024, S->Wa2T, DD, nullptr, S->Bea, DD);
  // kproj_table = k_table @ W_f2^T + b_f        (2000 x 512)
  sgemm2_k<true><<<dim3(16,4), 256>>>(k_tab, NC, W_f + DD, 2*DD, b_f, S->kproj_t, DD);
  // eaproj_table = x_table @ Bea^T + bias_ea    (4001 x 1024)
  sgemm2_k<true><<<dim3(32,8), 256>>>(x_tab, 2*NC+1, S->Bea, DD, S->bias_ea, S->eaproj_t, 2*DD);

  // ---- persistent memory recurrence ----
  memrec_kernel<<<128, 512, MEMREC_SMEM>>>(Mv0, W_f);

  // xproj = f @ W_ih^T + (b_ih + b_hh)          (6144 x 2048)
  sgemm2_k<true><<<dim3(48,16), 256>>>(S->f, ROWS, W_ih, DD, S->bihh, S->xproj, 4*DD);

  // ---- persistent hop-LSTM ----
  lstm_kernel<<<128, 256, LSTM_SMEM>>>(W_hh);

  // ---- head ----
  head_kernel<<<(BB*TT*32 + 255)/256, 256>>>(W_p, b_p, out);
}

// round 6
// speedup vs baseline: 1.9574x; 1.0259x over previous
#include <cuda_runtime.h>
#include <math.h>

#define BB 128
#define TT 48
#define DD 512
#define MM 64
#define NC 2000

typedef unsigned long long u64;

// ---------------- f32x2 packed helpers (sm_100+) -----------------------------
__device__ __forceinline__ u64 ffma2(u64 a, u64 b, u64 c){
  u64 d; asm("fma.rn.f32x2 %0, %1, %2, %3;" : "=l"(d) : "l"(a), "l"(b), "l"(c));
  return d;
}
__device__ __forceinline__ u64 f2pack(float lo, float hi){
  u64 r; asm("mov.b64 %0, {%1, %2};" : "=l"(r) : "f"(lo), "f"(hi)); return r;
}
__device__ __forceinline__ void f2unp(u64 v, float& lo, float& hi){
  asm("mov.b64 {%0, %1}, %2;" : "=f"(lo), "=f"(hi) : "l"(v));
}
__device__ __forceinline__ float f2sum(u64 v){
  float lo, hi; f2unp(v, lo, hi); return lo + hi;
}

// ---------------- static device scratch --------------------------------------
struct Scratch {
  float w_table[NC*MM];
  unsigned long long sig_table[NC*2];
  float kproj_t[2048*DD];
  float eaproj_t[4096*2*DD];
  float Aea[2*DD*DD];
  float Bea[2*DD*DD];
  float Sw[2*DD*DD];
  float WaT[DD*DD];
  float Wa2T[DD*DD];
  float bias_ea[2*DD];
  float rd[BB*DD];
  float f[TT*BB*DD];
  float ea[BB*2*DD];
  float xproj[TT*BB*4*DD];
  float H[(TT+1)*BB*DD];
  float C[(TT+1)*BB*DD];
  float bihh[4*DD];
  int src[TT*BB];
  int qidx[TT*BB];                // layout t*BB + b
  int xidx[TT*BB];
};
__device__ Scratch gS;

// group-local barrier counters: memrec 8 groups x 144 slots, lstm 4 x 48
#define MSLOTS 144
__device__ unsigned gBarM[8*MSLOTS];
__device__ unsigned gBarL[4*TT];

__device__ __forceinline__ float sigm(float x){ return 1.f/(1.f+expf(-x)); }

// Hot bounded-spin group barrier. Counters zeroed by combo kernel each replay.
__device__ __forceinline__ void gbar_g(volatile unsigned* ctr, int slot, unsigned nb){
  __syncthreads();
  if (threadIdx.x == 0){
    __threadfence();
    unsigned prev = atomicAdd((unsigned*)&ctr[slot], 1u);
    if (prev + 1u < nb){
      unsigned it = 0;
      while (ctr[slot] < nb && it < 1000000u) it++;
    }
    __threadfence();
  }
  __syncthreads();
}

// ---------------- combo setup kernel ----------------------------------------
// block ranges: [0, NB_A): elementwise inits + barrier reset
//               [NB_A, NB_A+128): bias_ea rows
//               [NB_A+128, NB_A+128+NC): addressing softmax per q id
#define EW_HC    (BB*DD)            // 65536
#define EW_IDX   (TT*BB)            // 6144
#define EW_BIHH  (4*DD)             // 2048
#define EW_TRANS (DD*DD)            // 262144
#define EW_STACK (DD*DD)            // 262144
#define EW_BARS  (8*MSLOTS + 4*TT)  // 1344
#define EW_TOTAL (EW_HC+EW_IDX+EW_BIHH+EW_TRANS+EW_STACK+EW_BARS)
#define NB_A ((EW_TOTAL + 255)/256)

__global__ __launch_bounds__(256) void combo_kernel(
    const int* __restrict__ q, const int* __restrict__ r,
    const float* __restrict__ hx0, const float* __restrict__ cx0,
    const float* __restrict__ bih, const float* __restrict__ bhh,
    const float* __restrict__ Wa,
    const float* __restrict__ We, const float* __restrict__ Wadd,
    const float* __restrict__ ba, const float* __restrict__ be,
    const float* __restrict__ badd,
    const float* __restrict__ Mk, const float* __restrict__ k_table)
{
  int blk = blockIdx.x;
  int tid = threadIdx.x;
  if (blk < NB_A){
    int i = blk*256 + tid;
    if (i < EW_HC){
      gS.H[i] = hx0[i % DD]; gS.C[i] = cx0[i % DD];
    } else if ((i -= EW_HC) < EW_IDX){
      int t = i / BB, b = i % BB;
      int qi = q[b*TT + t];
      int ri = r[b*TT + t];
      gS.qidx[i] = qi;
      gS.xidx[i] = qi + NC*ri;
    } else if ((i -= EW_IDX) < EW_BIHH){
      gS.bihh[i] = bih[i] + bhh[i];
    } else if ((i -= EW_BIHH) < EW_TRANS){
      int j = i / DD, k = i % DD;
      gS.WaT[i]  = Wa[(long)k*(2*DD) + j];
      gS.Wa2T[i] = Wa[(long)k*(2*DD) + DD + j];
    } else if ((i -= EW_TRANS) < EW_STACK){
      gS.Sw[i] = We[i]; gS.Sw[DD*DD + i] = Wadd[i];
    } else if ((i -= EW_STACK) < EW_BARS){
      if (i < 8*MSLOTS) gBarM[i] = 0u; else gBarL[i - 8*MSLOTS] = 0u;
    }
    return;
  }
  blk -= NB_A;
  if (blk < 128){
    // bias_ea[n] = dot(row_n, b_a) + (b_e|b_add)[n], 8 rows per block
    int n = blk*8 + (tid >> 5);
    int lane = tid & 31;
    const float* row = (n < DD) ? (We + (long)n*DD) : (Wadd + (long)(n-DD)*DD);
    float s = 0.f;
    for (int k = lane; k < DD; k += 32) s += row[k]*ba[k];
    #pragma unroll
    for (int o = 16; o > 0; o >>= 1) s += __shfl_down_sync(0xffffffffu, s, o);
    if (lane == 0) gS.bias_ea[n] = s + ((n < DD) ? be[n] : badd[n-DD]);
    return;
  }
  blk -= 128;
  // ---- addressing softmax + signature for q id = blk ----
  {
    int id = blk;
    __shared__ float kv[DD];
    __shared__ float lg[MM];
    __shared__ float eg[MM];
    __shared__ unsigned char ivb[MM];
    const float* kr = k_table + (long)id*DD;
    kv[tid] = kr[tid]; kv[tid+256] = kr[tid+256];
    __syncthreads();
    int m = tid >> 2, part = tid & 3;
    const ulonglong2* mk2 = (const ulonglong2*)(Mk + (long)m*DD + part*128);
    const ulonglong2* kv2 = (const ulonglong2*)(kv + part*128);
    u64 acc2 = 0;
    #pragma unroll 8
    for (int k4 = 0; k4 < 32; k4++){
      ulonglong2 m2 = mk2[k4], k2 = kv2[k4];
      acc2 = ffma2(m2.x, k2.x, acc2);
      acc2 = ffma2(m2.y, k2.y, acc2);
    }
    float s = f2sum(acc2);
    s += __shfl_down_sync(0xffffffffu, s, 2, 4);
    s += __shfl_down_sync(0xffffffffu, s, 1, 4);
    if (part == 0) lg[m] = s;
    __syncthreads();
    if (tid < MM){
      float sv = lg[tid];
      float mx = -1e30f;
      for (int mm = 0; mm < MM; mm++) mx = fmaxf(mx, lg[mm]);
      float ex = expf(sv - mx);
      eg[tid] = ex;
      __syncwarp(0xffffffffu);
      // need all eg; eg written by threads 0..63 across 2 warps -> syncthreads
    }
    __syncthreads();
    if (tid < MM){
      float sum = 0.f;
      for (int mm = 0; mm < MM; mm++) sum += eg[mm];
      float wv = eg[tid] / sum;
      gS.w_table[(long)id*MM + tid] = wv;
      float mval = fminf((wv - 0.075f)/(0.088f - 0.075f), (1.0f - wv)/(1.0f - 0.088f));
      mval = fmaxf(mval, 0.f);
      int iv = (mval >= 0.6f) ? 2 : ((mval >= 0.1f) ? 1 : 0);
      ivb[tid] = (unsigned char)iv;
    }
    __syncthreads();
    if (tid < 2){
      unsigned long long sg = 0ull;
      #pragma unroll
      for (int i2 = 0; i2 < 32; i2++) sg |= ((unsigned long long)ivb[tid*32 + i2]) << (2*i2);
      gS.sig_table[(long)id*2 + tid] = sg;
    }
  }
}

__global__ void src_kernel(){
  int b = blockIdx.x;
  int tid = threadIdx.x;  // 64 threads
  __shared__ unsigned long long s0[TT], s1[TT];
  if (tid < TT){
    int id = gS.qidx[tid*BB + b];
    s0[tid] = gS.sig_table[(long)id*2];
    s1[tid] = gS.sig_table[(long)id*2 + 1];
  }
  __syncthreads();
  if (tid < TT){
    int i = tid, sr = i - 1;
    unsigned long long a0 = s0[i], a1 = s1[i];
    for (int j = i - 1; j >= 0; j--){
      if (s0[j] == a0 && s1[j] == a1){ sr = j; break; }
    }
    gS.src[i*BB + b] = sr;
  }
}

// ---------------- 128x128x8 SGEMM via f32x2: C = A@W^T + bias ---------------
template<bool HB>
__global__ __launch_bounds__(256) void sgemm2_k(
    const float* __restrict__ A, int Mrows,
    const float* __restrict__ W, int ldw,
    const float* __restrict__ bias,
    float* __restrict__ C, int ldc)
{
  __shared__ u64 As2[8][128];
  __shared__ float Bs[8][128];
  int tid = threadIdx.x;
  int m0 = blockIdx.x * 128, n0 = blockIdx.y * 128;
  int tx = tid & 15, ty = tid >> 4;
  int lr = tid >> 1;
  int lk = (tid & 1) * 4;
  int mrow = m0 + lr;
  int mload = mrow < Mrows ? mrow : (Mrows - 1);
  const float4* Ap = (const float4*)(A + (long)mload*DD + lk);
  const float4* Wp = (const float4*)(W + (long)(n0 + lr)*ldw + lk);

  u64 acc2[8][4];
  #pragma unroll
  for (int i = 0; i < 8; i++)
    #pragma unroll
    for (int j = 0; j < 4; j++) acc2[i][j] = 0ull;

  for (int kb = 0; kb < 64; kb++){
    float4 av = Ap[kb*2];
    float4 bv = Wp[kb*2];
    As2[lk+0][lr] = f2pack(av.x, av.x);
    As2[lk+1][lr] = f2pack(av.y, av.y);
    As2[lk+2][lr] = f2pack(av.z, av.z);
    As2[lk+3][lr] = f2pack(av.w, av.w);
    Bs[lk+0][lr] = bv.x; Bs[lk+1][lr] = bv.y; Bs[lk+2][lr] = bv.z; Bs[lk+3][lr] = bv.w;
    __syncthreads();
    #pragma unroll
    for (int k = 0; k < 8; k++){
      const ulonglong2* a4 = (const ulonglong2*)&As2[k][ty*8];
      ulonglong2 t0 = a4[0], t1 = a4[1], t2 = a4[2], t3 = a4[3];
      u64 a2[8] = {t0.x, t0.y, t1.x, t1.y, t2.x, t2.y, t3.x, t3.y};
      float4 bl = *(const float4*)&Bs[k][tx*8];
      float4 bh = *(const float4*)&Bs[k][tx*8+4];
      u64 b2[4] = {f2pack(bl.x, bl.y), f2pack(bl.z, bl.w),
                   f2pack(bh.x, bh.y), f2pack(bh.z, bh.w)};
      #pragma unroll
      for (int i = 0; i < 8; i++)
        #pragma unroll
        for (int j = 0; j < 4; j++) acc2[i][j] = ffma2(a2[i], b2[j], acc2[i][j]);
    }
    __syncthreads();
  }
  #pragma unroll
  for (int i = 0; i < 8; i++){
    int m = m0 + ty*8 + i;
    if (m < Mrows){
      int n = n0 + tx*8;
      float c0,c1,c2,c3,c4,c5,c6,c7;
      f2unp(acc2[i][0], c0, c1); f2unp(acc2[i][1], c2, c3);
      f2unp(acc2[i][2], c4, c5); f2unp(acc2[i][3], c6, c7);
      float4 o0, o1;
      o0.x = c0 + (HB ? bias[n+0] : 0.f);
      o0.y = c1 + (HB ? bias[n+1] : 0.f);
      o0.z = c2 + (HB ? bias[n+2] : 0.f);
      o0.w = c3 + (HB ? bias[n+3] : 0.f);
      o1.x = c4 + (HB ? bias[n+4] : 0.f);
      o1.y = c5 + (HB ? bias[n+5] : 0.f);
      o1.z = c6 + (HB ? bias[n+6] : 0.f);
      o1.w = c7 + (HB ? bias[n+7] : 0.f);
      *(float4*)(C + (long)m*ldc + n)     = o0;
      *(float4*)(C + (long)m*ldc + n + 4) = o1;
    }
  }
}

// ---------------- persistent memory recurrence ------------------------------
// 128 blocks x 512 thr. Deps confined to 16-block groups sharing bq=bid>>4.
#define MEMREC_SMEM ((MM*DD + 16*516 + 128)*4)

__global__ __launch_bounds__(512) void memrec_kernel(
    const float* __restrict__ Mv0, const float* __restrict__ W_f)
{
  extern __shared__ float sm[];
  float* mem_s = sm;                 // 64*512
  float* tile  = sm + MM*DD;         // 16*516
  float* w0s   = tile + 16*516;      // 64
  float* w1s   = w0s + 64;           // 64
  int bid = blockIdx.x, tid = threadIdx.x;
  int bq = bid >> 4, cq = bid & 15;
  int b0 = bq * 16;
  int myb = bid;
  volatile unsigned* ctr = gBarM + bq*MSLOTS;

  {
    const float4* s4 = (const float4*)Mv0;
    float4* d4 = (float4*)mem_s;
    #pragma unroll 4
    for (int i = tid; i < MM*DD/4; i += 512) d4[i] = s4[i];
  }
  if (tid < MM){
    int qid = gS.qidx[myb];   // t = 0
    w0s[tid] = gS.w_table[(long)qid*MM + tid];
  }
  __syncthreads();
  {
    int d = tid;
    float acc = 0.f;
    #pragma unroll 8
    for (int m = 0; m < MM; m++) acc += w0s[m]*mem_s[m*DD + d];
    gS.rd[myb*DD + d] = acc;
  }
  int slot = 0;
  gbar_g(ctr, slot++, 16);

  for (int t = 0; t < TT; t++){
    // ---- stage1: f_t = tanh(Wf1 @ rd + kproj_table[q]) ----
    {
      for (int i = tid; i < 16*DD/4; i += 512){
        int rr = i >> 7, k4 = i & 127;
        *(float4*)(tile + rr*516 + k4*4) = *(const float4*)(gS.rd + (b0+rr)*DD + k4*4);
      }
      __syncthreads();
      int bl = tid & 15, cl = tid >> 4;
      int c = cq*32 + cl;
      const ulonglong2* wr2 = (const ulonglong2*)(W_f + (long)c*(2*DD));
      const ulonglong2* rv2 = (const ulonglong2*)(tile + bl*516);
      u64 acc2 = 0;
      #pragma unroll 8
      for (int k4 = 0; k4 < 128; k4++){
        ulonglong2 wv = wr2[k4], rv = rv2[k4];
        acc2 = ffma2(wv.x, rv.x, acc2);
        acc2 = ffma2(wv.y, rv.y, acc2);
      }
      int brow = b0 + bl;
      int qid = gS.qidx[t*BB + brow];
      float acc = f2sum(acc2) + gS.kproj_t[(long)qid*DD + c];
      gS.f[((long)t*BB + brow)*DD + c] = tanhf(acc);
    }
    if (t == TT-1) break;
    gbar_g(ctr, slot++, 16);

    // ---- stage2: [e|a]_t = act(Aea @ f_t + eaproj_table[x]) ----
    {
      for (int i = tid; i < 16*DD/4; i += 512){
        int rr = i >> 7, k4 = i & 127;
        *(float4*)(tile + rr*516 + k4*4) =
            *(const float4*)(gS.f + ((long)t*BB + b0 + rr)*DD + k4*4);
      }
      __syncthreads();
      int bl = tid & 15, cp = tid >> 4;
      int c0 = cq*64 + cp*2;
      const ulonglong2* a0 = (const ulonglong2*)(gS.Aea + (long)c0*DD);
      const ulonglong2* a1 = (const ulonglong2*)(gS.Aea + (long)(c0+1)*DD);
      const ulonglong2* fv2 = (const ulonglong2*)(tile + bl*516);
      u64 acc0_2 = 0, acc1_2 = 0;
      #pragma unroll 8
      for (int k4 = 0; k4 < 128; k4++){
        ulonglong2 fv = fv2[k4];
        ulonglong2 w0v = a0[k4], w1v = a1[k4];
        acc0_2 = ffma2(w0v.x, fv.x, acc0_2);
        acc0_2 = ffma2(w0v.y, fv.y, acc0_2);
        acc1_2 = ffma2(w1v.x, fv.x, acc1_2);
        acc1_2 = ffma2(w1v.y, fv.y, acc1_2);
      }
      int brow = b0 + bl;
      int xid = gS.xidx[t*BB + brow];
      const float* ep = gS.eaproj_t + (long)xid*(2*DD);
      float v0 = f2sum(acc0_2) + ep[c0];
      float v1 = f2sum(acc1_2) + ep[c0+1];
      float* eo = gS.ea + brow*(2*DD);
      if (cq < 8){ eo[c0] = sigm(v0); eo[c0+1] = sigm(v1); }
      else       { eo[c0] = tanhf(v0); eo[c0+1] = tanhf(v1); }
    }
    gbar_g(ctr, slot++, 16);

    // ---- stage3: mem update (SMEM-resident) + rd_{t+1} ----
    {
      if (tid < MM){
        int q0 = gS.qidx[t*BB + myb];
        int q1 = gS.qidx[(t+1)*BB + myb];
        w0s[tid] = gS.w_table[(long)q0*MM + tid];
        w1s[tid] = gS.w_table[(long)q1*MM + tid];
      }
      __syncthreads();
      int d = tid;
      float ev = gS.ea[myb*(2*DD) + d];
      float av = gS.ea[myb*(2*DD) + DD + d];
      float acc = 0.f;
      #pragma unroll 8
      for (int m = 0; m < MM; m++){
        float v = mem_s[m*DD + d];
        v = v*(1.f - w0s[m]*ev) + w0s[m]*av;
        mem_s[m*DD + d] = v;
        acc += w1s[m]*v;
      }
      gS.rd[myb*DD + d] = acc;
    }
    gbar_g(ctr, slot++, 16);
  }
}

// ---------------- persistent hop-LSTM ---------------------------------------
// 128 blocks x 256 thr. Deps confined to 32-block groups sharing b0=bid>>5.
#define LSTM_SMEM ((64*516 + 32*512)*4 + 128)

__global__ __launch_bounds__(256) void lstm_kernel(const float* __restrict__ Whh){
  extern __shared__ float sm[];
  float* Ws = sm;                        // 64 rows x 516 (padded)
  float* Hs = sm + 64*516;               // 32 x 512
  int* ssrc = (int*)(Hs + 32*512);       // 32
  int bid = blockIdx.x, tid = threadIdx.x;
  int n0 = (bid & 31) * 16;
  int b0 = (bid >> 5) * 32;
  volatile unsigned* ctr = gBarL + (bid >> 5)*TT;

  {
    float4* WsV = (float4*)Ws;
    for (int i = tid; i < 64*128; i += 256){
      int r = i >> 7, k4 = i & 127;
      int g = r >> 4, n = r & 15;
      WsV[(long)r*129 + k4] =
          ((const float4*)(Whh + ((long)(g*DD + n0 + n))*DD))[k4];
    }
  }
  __syncthreads();

  int n_local = tid & 15;
  int bg = tid >> 4;
  const ulonglong2* WsV2 = (const ulonglong2*)Ws;
  const ulonglong2* HsV2 = (const ulonglong2*)Hs;
  float4* HsV = (float4*)Hs;

  for (int t = 0; t < TT; t++){
    if (tid < 32) ssrc[tid] = gS.src[t*BB + b0 + tid];
    __syncthreads();
    for (int i = tid; i < 32*128; i += 256){
      int row = i >> 7, k4 = i & 127;
      long hrow = ((long)(ssrc[row]+1)*BB + (b0 + row))*DD;
      HsV[row*128 + k4] = ((const float4*)(gS.H + hrow))[k4];
    }
    __syncthreads();

    u64 acc2[2][4];
    #pragma unroll
    for (int bi = 0; bi < 2; bi++)
      #pragma unroll
      for (int g = 0; g < 4; g++) acc2[bi][g] = 0ull;

    #pragma unroll 2
    for (int k4 = 0; k4 < 128; k4++){
      ulonglong2 h0 = HsV2[(bg*2+0)*128 + k4];
      ulonglong2 h1 = HsV2[(bg*2+1)*128 + k4];
      #pragma unroll
      for (int g = 0; g < 4; g++){
        ulonglong2 wv = WsV2[(long)(g*16 + n_local)*129 + k4];
        acc2[0][g] = ffma2(wv.x, h0.x, acc2[0][g]);
        acc2[0][g] = ffma2(wv.y, h0.y, acc2[0][g]);
        acc2[1][g] = ffma2(wv.x, h1.x, acc2[1][g]);
        acc2[1][g] = ffma2(wv.y, h1.y, acc2[1][g]);
      }
    }

    #pragma unroll
    for (int bi = 0; bi < 2; bi++){
      int bl = bg*2 + bi;
      int b = b0 + bl;
      int srcp = ssrc[bl] + 1;
      int n = n0 + n_local;
      const float* xp = gS.xproj + ((long)t*BB + b)*(4*DD);
      float gi = f2sum(acc2[bi][0]) + xp[n];
      float gf = f2sum(acc2[bi][1]) + xp[DD + n];
      float gg = f2sum(acc2[bi][2]) + xp[2*DD + n];
      float go = f2sum(acc2[bi][3]) + xp[3*DD + n];
      float cin = gS.C[((long)srcp*BB + b)*DD + n];
      float c = sigm(gf)*cin + sigm(gi)*tanhf(gg);
      float h = sigm(go)*tanhf(c);
      long o = ((long)(t+1)*BB + b)*DD + n;
      gS.H[o] = h;
      gS.C[o] = c;
    }
    if (t < TT-1) gbar_g(ctr, t, 32);
  }
}

// ---------------- prediction head -------------------------------------------
__global__ void head_kernel(const float* __restrict__ Wp, const float* __restrict__ bp,
                            float* __restrict__ out){
  int gw = (blockIdx.x*blockDim.x + threadIdx.x) >> 5;
  int lane = threadIdx.x & 31;
  if (gw >= BB*TT) return;
  int b = gw / TT, t = gw % TT;
  const float* h = gS.H + ((long)(t+1)*BB + b)*DD;
  float s = 0.f;
  for (int j = lane; j < DD; j += 32) s += h[j]*Wp[j];
  #pragma unroll
  for (int o = 16; o > 0; o >>= 1) s += __shfl_down_sync(0xffffffffu, s, o);
  if (lane == 0) out[b*TT + t] = sigm(s + bp[0]);
}

// ---------------- host orchestration ----------------------------------------
extern "C" void kernel_launch(void* const* d_in, const int* in_sizes, int n_in,
                              void* d_out, int out_size){
  (void)in_sizes; (void)n_in; (void)out_size;
  const int*   q     = (const int*)d_in[0];
  const int*   r     = (const int*)d_in[1];
  const float* Mk    = (const float*)d_in[2];
  const float* Mv0   = (const float*)d_in[3];
  const float* k_tab = (const float*)d_in[4];
  const float* x_tab = (const float*)d_in[5];
  const float* W_e   = (const float*)d_in[6];
  const float* b_e   = (const float*)d_in[7];
  const float* W_add = (const float*)d_in[8];
  const float* b_add = (const float*)d_in[9];
  const float* W_a   = (const float*)d_in[10];
  const float* b_a   = (const float*)d_in[11];
  const float* W_f   = (const float*)d_in[12];
  const float* b_f   = (const float*)d_in[13];
  const float* W_ih  = (const float*)d_in[14];
  const float* W_hh  = (const float*)d_in[15];
  const float* b_ih  = (const float*)d_in[16];
  const float* b_hh  = (const float*)d_in[17];
  const float* hx0   = (const float*)d_in[18];
  const float* cx0   = (const float*)d_in[19];
  const float* W_p   = (const float*)d_in[20];
  const float* b_p   = (const float*)d_in[21];
  float* out = (float*)d_out;

  Scratch* S = nullptr;
  cudaGetSymbolAddress((void**)&S, gS);

  cudaFuncSetAttribute(memrec_kernel, cudaFuncAttributeMaxDynamicSharedMemorySize, MEMREC_SMEM);
  cudaFuncSetAttribute(lstm_kernel,   cudaFuncAttributeMaxDynamicSharedMemorySize, LSTM_SMEM);

  const int ROWS = TT*BB; // 6144

  // ---- fused setup (inits + barrier reset + bias_ea + addressing) ----
  combo_kernel<<<NB_A + 128 + NC, 256>>>(q, r, hx0, cx0, b_ih, b_hh, W_a,
                                         W_e, W_add, b_a, b_e, b_add, Mk, k_tab);
  src_kernel<<<BB, 64>>>();

  // Aea = Sw @ WaT^T ; Bea = Sw @ Wa2T^T        (1024 x 512 each)
  sgemm2_k<false><<<dim3(8,4), 256>>>(S->Sw, 1024, S->WaT, DD, nullptr, S->Aea, DD);
  sgemm2_k<false><<<dim3(8,4), 256>>>(S->Sw, 1024, S->Wa2T, DD, nullptr, S->Bea, DD);
  // kproj_table = k_table @ W_f2^T + b_f        (2000 x 512)
  sgemm2_k<true><<<dim3(16,4), 256>>>(k_tab, NC, W_f + DD, 2*DD, b_f, S->kproj_t, DD);
  // eaproj_table = x_table @ Bea^T + bias_ea    (4001 x 1024)
  sgemm2_k<true><<<dim3(32,8), 256>>>(x_tab, 2*NC+1, S->Bea, DD, S->bias_ea, S->eaproj_t, 2*DD);

  // ---- persistent memory recurrence ----
  memrec_kernel<<<128, 512, MEMREC_SMEM>>>(Mv0, W_f);

  // xproj = f @ W_ih^T + (b_ih + b_hh)          (6144 x 2048)
  sgemm2_k<true><<<dim3(48,16), 256>>>(S->f, ROWS, W_ih, DD, S->bihh, S->xproj, 4*DD);

  // ---- persistent hop-LSTM ----
  lstm_kernel<<<128, 256, LSTM_SMEM>>>(W_hh);

  // ---- head ----
  head_kernel<<<(BB*TT*32 + 255)/256, 256>>>(W_p, b_p, out);
}

// round 7
// speedup vs baseline: 2.0487x; 1.0467x over previous
#include <cuda_runtime.h>
#include <math.h>

#define BB 128
#define TT 48
#define DD 512
#define MM 64
#define NC 2000

typedef unsigned long long u64;

// ---------------- f32x2 packed helpers (sm_100+) -----------------------------
__device__ __forceinline__ u64 ffma2(u64 a, u64 b, u64 c){
  u64 d; asm("fma.rn.f32x2 %0, %1, %2, %3;" : "=l"(d) : "l"(a), "l"(b), "l"(c));
  return d;
}
__device__ __forceinline__ u64 f2pack(float lo, float hi){
  u64 r; asm("mov.b64 %0, {%1, %2};" : "=l"(r) : "f"(lo), "f"(hi)); return r;
}
__device__ __forceinline__ void f2unp(u64 v, float& lo, float& hi){
  asm("mov.b64 {%0, %1}, %2;" : "=f"(lo), "=f"(hi) : "l"(v));
}
__device__ __forceinline__ float f2sum(u64 v){
  float lo, hi; f2unp(v, lo, hi); return lo + hi;
}

// ---------------- static device scratch --------------------------------------
struct Scratch {
  float w_table[NC*MM];
  unsigned long long sig_table[NC*2];
  float kproj_t[2048*DD];
  float eaproj_t[4096*2*DD];
  float Aea[2*DD*DD];
  float Bea[2*DD*DD];
  float Sw[2*DD*DD];
  float WaT[DD*DD];
  float Wa2T[DD*DD];
  float bias_ea[2*DD];
  float rd[BB*DD];
  float f[TT*BB*DD];
  float ea[BB*2*DD];
  float xproj[TT*BB*4*DD];
  float H[(TT+1)*BB*DD];
  float C[(TT+1)*BB*DD];
  float bihh[4*DD];
  int src[TT*BB];
  int qidx[TT*BB];                // layout t*BB + b
  int xidx[TT*BB];
};
__device__ Scratch gS;

// group-local barrier counters: memrec 8 groups x 144 slots, lstm 4 x 48
#define MSLOTS 144
__device__ unsigned gBarM[8*MSLOTS];
__device__ unsigned gBarL[4*TT];

__device__ __forceinline__ float sigm(float x){ return 1.f/(1.f+expf(-x)); }

// Group barrier via release/acquire atomics (no membar.gl / no L1 flush).
// Producer writes -> __syncthreads (cta order) -> t0 atom.add.acq_rel (release).
// Consumer t0 ld.acquire sees count==nb -> __syncthreads -> block reads.
__device__ __forceinline__ void gbar_g(unsigned* ctr, int slot, unsigned nb){
  __syncthreads();
  if (threadIdx.x == 0){
    unsigned prev;
    asm volatile("atom.add.acq_rel.gpu.u32 %0, [%1], 1;"
                 : "=r"(prev) : "l"(ctr + slot) : "memory");
    if (prev + 1u < nb){
      unsigned v = 0, it = 0;
      do {
        asm volatile("ld.acquire.gpu.u32 %0, [%1];"
                     : "=r"(v) : "l"(ctr + slot) : "memory");
      } while (v < nb && ++it < 2000000u);
    }
  }
  __syncthreads();
}

// ---------------- combo setup kernel ----------------------------------------
#define EW_HC    (BB*DD)            // 65536
#define EW_IDX   (TT*BB)            // 6144
#define EW_BIHH  (4*DD)             // 2048
#define EW_TRANS (DD*DD)            // 262144
#define EW_STACK (DD*DD)            // 262144
#define EW_BARS  (8*MSLOTS + 4*TT)  // 1344
#define EW_TOTAL (EW_HC+EW_IDX+EW_BIHH+EW_TRANS+EW_STACK+EW_BARS)
#define NB_A ((EW_TOTAL + 255)/256)

__global__ __launch_bounds__(256) void combo_kernel(
    const int* __restrict__ q, const int* __restrict__ r,
    const float* __restrict__ hx0, const float* __restrict__ cx0,
    const float* __restrict__ bih, const float* __restrict__ bhh,
    const float* __restrict__ Wa,
    const float* __restrict__ We, const float* __restrict__ Wadd,
    const float* __restrict__ ba, const float* __restrict__ be,
    const float* __restrict__ badd,
    const float* __restrict__ Mk, const float* __restrict__ k_table)
{
  int blk = blockIdx.x;
  int tid = threadIdx.x;
  if (blk < NB_A){
    int i = blk*256 + tid;
    if (i < EW_HC){
      gS.H[i] = hx0[i % DD]; gS.C[i] = cx0[i % DD];
    } else if ((i -= EW_HC) < EW_IDX){
      int t = i / BB, b = i % BB;
      int qi = q[b*TT + t];
      int ri = r[b*TT + t];
      gS.qidx[i] = qi;
      gS.xidx[i] = qi + NC*ri;
    } else if ((i -= EW_IDX) < EW_BIHH){
      gS.bihh[i] = bih[i] + bhh[i];
    } else if ((i -= EW_BIHH) < EW_TRANS){
      int j = i / DD, k = i % DD;
      gS.WaT[i]  = Wa[(long)k*(2*DD) + j];
      gS.Wa2T[i] = Wa[(long)k*(2*DD) + DD + j];
    } else if ((i -= EW_TRANS) < EW_STACK){
      gS.Sw[i] = We[i]; gS.Sw[DD*DD + i] = Wadd[i];
    } else if ((i -= EW_STACK) < EW_BARS){
      if (i < 8*MSLOTS) gBarM[i] = 0u; else gBarL[i - 8*MSLOTS] = 0u;
    }
    return;
  }
  blk -= NB_A;
  if (blk < 128){
    int n = blk*8 + (tid >> 5);
    int lane = tid & 31;
    const float* row = (n < DD) ? (We + (long)n*DD) : (Wadd + (long)(n-DD)*DD);
    float s = 0.f;
    for (int k = lane; k < DD; k += 32) s += row[k]*ba[k];
    #pragma unroll
    for (int o = 16; o > 0; o >>= 1) s += __shfl_down_sync(0xffffffffu, s, o);
    if (lane == 0) gS.bias_ea[n] = s + ((n < DD) ? be[n] : badd[n-DD]);
    return;
  }
  blk -= 128;
  // ---- addressing softmax + signature for q id = blk ----
  {
    int id = blk;
    __shared__ float kv[DD];
    __shared__ float lg[MM];
    __shared__ float eg[MM];
    __shared__ unsigned char ivb[MM];
    const float* kr = k_table + (long)id*DD;
    kv[tid] = kr[tid]; kv[tid+256] = kr[tid+256];
    __syncthreads();
    int m = tid >> 2, part = tid & 3;
    const ulonglong2* mk2 = (const ulonglong2*)(Mk + (long)m*DD + part*128);
    const ulonglong2* kv2 = (const ulonglong2*)(kv + part*128);
    u64 acc2 = 0;
    #pragma unroll 8
    for (int k4 = 0; k4 < 32; k4++){
      ulonglong2 m2 = mk2[k4], k2 = kv2[k4];
      acc2 = ffma2(m2.x, k2.x, acc2);
      acc2 = ffma2(m2.y, k2.y, acc2);
    }
    float s = f2sum(acc2);
    s += __shfl_down_sync(0xffffffffu, s, 2, 4);
    s += __shfl_down_sync(0xffffffffu, s, 1, 4);
    if (part == 0) lg[m] = s;
    __syncthreads();
    if (tid < MM){
      float sv = lg[tid];
      float mx = -1e30f;
      for (int mm = 0; mm < MM; mm++) mx = fmaxf(mx, lg[mm]);
      eg[tid] = expf(sv - mx);
    }
    __syncthreads();
    if (tid < MM){
      float sum = 0.f;
      for (int mm = 0; mm < MM; mm++) sum += eg[mm];
      float wv = eg[tid] / sum;
      gS.w_table[(long)id*MM + tid] = wv;
      float mval = fminf((wv - 0.075f)/(0.088f - 0.075f), (1.0f - wv)/(1.0f - 0.088f));
      mval = fmaxf(mval, 0.f);
      int iv = (mval >= 0.6f) ? 2 : ((mval >= 0.1f) ? 1 : 0);
      ivb[tid] = (unsigned char)iv;
    }
    __syncthreads();
    if (tid < 2){
      unsigned long long sg = 0ull;
      #pragma unroll
      for (int i2 = 0; i2 < 32; i2++) sg |= ((unsigned long long)ivb[tid*32 + i2]) << (2*i2);
      gS.sig_table[(long)id*2 + tid] = sg;
    }
  }
}

__global__ void src_kernel(){
  int b = blockIdx.x;
  int tid = threadIdx.x;  // 64 threads
  __shared__ unsigned long long s0[TT], s1[TT];
  if (tid < TT){
    int id = gS.qidx[tid*BB + b];
    s0[tid] = gS.sig_table[(long)id*2];
    s1[tid] = gS.sig_table[(long)id*2 + 1];
  }
  __syncthreads();
  if (tid < TT){
    int i = tid, sr = i - 1;
    unsigned long long a0 = s0[i], a1 = s1[i];
    for (int j = i - 1; j >= 0; j--){
      if (s0[j] == a0 && s1[j] == a1){ sr = j; break; }
    }
    gS.src[i*BB + b] = sr;
  }
}

// ---------------- double-buffered 128x128x8 SGEMM body ----------------------
// C = A @ W^T (+bias). One __syncthreads per K-chunk; prefetch overlaps compute.
template<bool HB>
__device__ __forceinline__ void sgemm_body(
    const float* __restrict__ A, int Mrows,
    const float* __restrict__ W, int ldw,
    const float* __restrict__ bias,
    float* __restrict__ C, int ldc,
    int m0, int n0)
{
  __shared__ u64 As2[2][8][128];
  __shared__ float Bs[2][8][128];
  int tid = threadIdx.x;
  int tx = tid & 15, ty = tid >> 4;
  int lr = tid >> 1;
  int lk = (tid & 1) * 4;
  int mrow = m0 + lr;
  int mload = mrow < Mrows ? mrow : (Mrows - 1);
  const float4* Ap = (const float4*)(A + (long)mload*DD + lk);
  const float4* Wp = (const float4*)(W + (long)(n0 + lr)*ldw + lk);

  u64 acc2[8][4];
  #pragma unroll
  for (int i = 0; i < 8; i++)
    #pragma unroll
    for (int j = 0; j < 4; j++) acc2[i][j] = 0ull;

  // preload chunk 0
  float4 av = Ap[0];
  float4 bv = Wp[0];
  As2[0][lk+0][lr] = f2pack(av.x, av.x);
  As2[0][lk+1][lr] = f2pack(av.y, av.y);
  As2[0][lk+2][lr] = f2pack(av.z, av.z);
  As2[0][lk+3][lr] = f2pack(av.w, av.w);
  Bs[0][lk+0][lr] = bv.x; Bs[0][lk+1][lr] = bv.y;
  Bs[0][lk+2][lr] = bv.z; Bs[0][lk+3][lr] = bv.w;
  __syncthreads();

  for (int kb = 0; kb < 64; kb++){
    int cur = kb & 1, nxt = cur ^ 1;
    if (kb < 63){
      av = Ap[(kb+1)*2];
      bv = Wp[(kb+1)*2];
    }
    #pragma unroll
    for (int k = 0; k < 8; k++){
      const ulonglong2* a4 = (const ulonglong2*)&As2[cur][k][ty*8];
      ulonglong2 t0 = a4[0], t1 = a4[1], t2 = a4[2], t3 = a4[3];
      u64 a2[8] = {t0.x, t0.y, t1.x, t1.y, t2.x, t2.y, t3.x, t3.y};
      float4 bl = *(const float4*)&Bs[cur][k][tx*8];
      float4 bh = *(const float4*)&Bs[cur][k][tx*8+4];
      u64 b2[4] = {f2pack(bl.x, bl.y), f2pack(bl.z, bl.w),
                   f2pack(bh.x, bh.y), f2pack(bh.z, bh.w)};
      #pragma unroll
      for (int i = 0; i < 8; i++)
        #pragma unroll
        for (int j = 0; j < 4; j++) acc2[i][j] = ffma2(a2[i], b2[j], acc2[i][j]);
    }
    if (kb < 63){
      As2[nxt][lk+0][lr] = f2pack(av.x, av.x);
      As2[nxt][lk+1][lr] = f2pack(av.y, av.y);
      As2[nxt][lk+2][lr] = f2pack(av.z, av.z);
      As2[nxt][lk+3][lr] = f2pack(av.w, av.w);
      Bs[nxt][lk+0][lr] = bv.x; Bs[nxt][lk+1][lr] = bv.y;
      Bs[nxt][lk+2][lr] = bv.z; Bs[nxt][lk+3][lr] = bv.w;
    }
    __syncthreads();
  }
  #pragma unroll
  for (int i = 0; i < 8; i++){
    int m = m0 + ty*8 + i;
    if (m < Mrows){
      int n = n0 + tx*8;
      float c0,c1,c2,c3,c4,c5,c6,c7;
      f2unp(acc2[i][0], c0, c1); f2unp(acc2[i][1], c2, c3);
      f2unp(acc2[i][2], c4, c5); f2unp(acc2[i][3], c6, c7);
      float4 o0, o1;
      o0.x = c0 + (HB ? bias[n+0] : 0.f);
      o0.y = c1 + (HB ? bias[n+1] : 0.f);
      o0.z = c2 + (HB ? bias[n+2] : 0.f);
      o0.w = c3 + (HB ? bias[n+3] : 0.f);
      o1.x = c4 + (HB ? bias[n+4] : 0.f);
      o1.y = c5 + (HB ? bias[n+5] : 0.f);
      o1.z = c6 + (HB ? bias[n+6] : 0.f);
      o1.w = c7 + (HB ? bias[n+7] : 0.f);
      *(float4*)(C + (long)m*ldc + n)     = o0;
      *(float4*)(C + (long)m*ldc + n + 4) = o1;
    }
  }
}

template<bool HB>
__global__ __launch_bounds__(256,2) void sgemm2_k(
    const float* __restrict__ A, int Mrows,
    const float* __restrict__ W, int ldw,
    const float* __restrict__ bias,
    float* __restrict__ C, int ldc)
{
  sgemm_body<HB>(A, Mrows, W, ldw, bias, C, ldc, blockIdx.x*128, blockIdx.y*128);
}

// Dual GEMM: blockIdx.y < 4 -> Aea = Sw @ WaT^T ; else -> Bea = Sw @ Wa2T^T
__global__ __launch_bounds__(256,2) void sgemm2_dual_k(
    const float* __restrict__ Sw,
    const float* __restrict__ W0, const float* __restrict__ W1,
    float* __restrict__ C0, float* __restrict__ C1)
{
  int by = blockIdx.y;
  if (by < 4)
    sgemm_body<false>(Sw, 1024, W0, DD, nullptr, C0, DD, blockIdx.x*128, by*128);
  else
    sgemm_body<false>(Sw, 1024, W1, DD, nullptr, C1, DD, blockIdx.x*128, (by-4)*128);
}

// ---------------- persistent memory recurrence ------------------------------
#define MEMREC_SMEM ((MM*DD + 16*516 + 128)*4)

__global__ __launch_bounds__(512) void memrec_kernel(
    const float* __restrict__ Mv0, const float* __restrict__ W_f)
{
  extern __shared__ float sm[];
  float* mem_s = sm;                 // 64*512
  float* tile  = sm + MM*DD;         // 16*516
  float* w0s   = tile + 16*516;      // 64
  float* w1s   = w0s + 64;           // 64
  int bid = blockIdx.x, tid = threadIdx.x;
  int bq = bid >> 4, cq = bid & 15;
  int b0 = bq * 16;
  int myb = bid;
  unsigned* ctr = gBarM + bq*MSLOTS;

  {
    const float4* s4 = (const float4*)Mv0;
    float4* d4 = (float4*)mem_s;
    #pragma unroll 4
    for (int i = tid; i < MM*DD/4; i += 512) d4[i] = s4[i];
  }
  if (tid < MM){
    int qid = gS.qidx[myb];   // t = 0
    w0s[tid] = gS.w_table[(long)qid*MM + tid];
  }
  __syncthreads();
  {
    int d = tid;
    float acc = 0.f;
    #pragma unroll 8
    for (int m = 0; m < MM; m++) acc += w0s[m]*mem_s[m*DD + d];
    gS.rd[myb*DD + d] = acc;
  }
  int slot = 0;
  gbar_g(ctr, slot++, 16);

  for (int t = 0; t < TT; t++){
    // ---- stage1: f_t = tanh(Wf1 @ rd + kproj_table[q]) ----
    {
      for (int i = tid; i < 16*DD/4; i += 512){
        int rr = i >> 7, k4 = i & 127;
        *(float4*)(tile + rr*516 + k4*4) = *(const float4*)(gS.rd + (b0+rr)*DD + k4*4);
      }
      __syncthreads();
      int bl = tid & 15, cl = tid >> 4;
      int c = cq*32 + cl;
      const ulonglong2* wr2 = (const ulonglong2*)(W_f + (long)c*(2*DD));
      const ulonglong2* rv2 = (const ulonglong2*)(tile + bl*516);
      u64 acc2 = 0;
      #pragma unroll 8
      for (int k4 = 0; k4 < 128; k4++){
        ulonglong2 wv = wr2[k4], rv = rv2[k4];
        acc2 = ffma2(wv.x, rv.x, acc2);
        acc2 = ffma2(wv.y, rv.y, acc2);
      }
      int brow = b0 + bl;
      int qid = gS.qidx[t*BB + brow];
      float acc = f2sum(acc2) + gS.kproj_t[(long)qid*DD + c];
      gS.f[((long)t*BB + brow)*DD + c] = tanhf(acc);
    }
    if (t == TT-1) break;
    gbar_g(ctr, slot++, 16);

    // ---- stage2: [e|a]_t = act(Aea @ f_t + eaproj_table[x]) ----
    {
      for (int i = tid; i < 16*DD/4; i += 512){
        int rr = i >> 7, k4 = i & 127;
        *(float4*)(tile + rr*516 + k4*4) =
            *(const float4*)(gS.f + ((long)t*BB + b0 + rr)*DD + k4*4);
      }
      __syncthreads();
      int bl = tid & 15, cp = tid >> 4;
      int c0 = cq*64 + cp*2;
      const ulonglong2* a0 = (const ulonglong2*)(gS.Aea + (long)c0*DD);
      const ulonglong2* a1 = (const ulonglong2*)(gS.Aea + (long)(c0+1)*DD);
      const ulonglong2* fv2 = (const ulonglong2*)(tile + bl*516);
      u64 acc0_2 = 0, acc1_2 = 0;
      #pragma unroll 8
      for (int k4 = 0; k4 < 128; k4++){
        ulonglong2 fv = fv2[k4];
        ulonglong2 w0v = a0[k4], w1v = a1[k4];
        acc0_2 = ffma2(w0v.x, fv.x, acc0_2);
        acc0_2 = ffma2(w0v.y, fv.y, acc0_2);
        acc1_2 = ffma2(w1v.x, fv.x, acc1_2);
        acc1_2 = ffma2(w1v.y, fv.y, acc1_2);
      }
      int brow = b0 + bl;
      int xid = gS.xidx[t*BB + brow];
      const float* ep = gS.eaproj_t + (long)xid*(2*DD);
      float v0 = f2sum(acc0_2) + ep[c0];
      float v1 = f2sum(acc1_2) + ep[c0+1];
      float* eo = gS.ea + brow*(2*DD);
      if (cq < 8){ eo[c0] = sigm(v0); eo[c0+1] = sigm(v1); }
      else       { eo[c0] = tanhf(v0); eo[c0+1] = tanhf(v1); }
    }
    gbar_g(ctr, slot++, 16);

    // ---- stage3: mem update (SMEM-resident) + rd_{t+1} ----
    {
      if (tid < MM){
        int q0 = gS.qidx[t*BB + myb];
        int q1 = gS.qidx[(t+1)*BB + myb];
        w0s[tid] = gS.w_table[(long)q0*MM + tid];
        w1s[tid] = gS.w_table[(long)q1*MM + tid];
      }
      __syncthreads();
      int d = tid;
      float ev = gS.ea[myb*(2*DD) + d];
      float av = gS.ea[myb*(2*DD) + DD + d];
      float acc = 0.f;
      #pragma unroll 8
      for (int m = 0; m < MM; m++){
        float v = mem_s[m*DD + d];
        v = v*(1.f - w0s[m]*ev) + w0s[m]*av;
        mem_s[m*DD + d] = v;
        acc += w1s[m]*v;
      }
      gS.rd[myb*DD + d] = acc;
    }
    gbar_g(ctr, slot++, 16);
  }
}

// ---------------- persistent hop-LSTM ---------------------------------------
#define LSTM_SMEM ((64*516 + 32*512)*4 + 128)

__global__ __launch_bounds__(256) void lstm_kernel(const float* __restrict__ Whh){
  extern __shared__ float sm[];
  float* Ws = sm;                        // 64 rows x 516 (padded)
  float* Hs = sm + 64*516;               // 32 x 512
  int* ssrc = (int*)(Hs + 32*512);       // 32
  int bid = blockIdx.x, tid = threadIdx.x;
  int n0 = (bid & 31) * 16;
  int b0 = (bid >> 5) * 32;
  unsigned* ctr = gBarL + (bid >> 5)*TT;

  {
    float4* WsV = (float4*)Ws;
    for (int i = tid; i < 64*128; i += 256){
      int r = i >> 7, k4 = i & 127;
      int g = r >> 4, n = r & 15;
      WsV[(long)r*129 + k4] =
          ((const float4*)(Whh + ((long)(g*DD + n0 + n))*DD))[k4];
    }
  }
  __syncthreads();

  int n_local = tid & 15;
  int bg = tid >> 4;
  const ulonglong2* WsV2 = (const ulonglong2*)Ws;
  const ulonglong2* HsV2 = (const ulonglong2*)Hs;
  float4* HsV = (float4*)Hs;

  for (int t = 0; t < TT; t++){
    if (tid < 32) ssrc[tid] = gS.src[t*BB + b0 + tid];
    __syncthreads();
    for (int i = tid; i < 32*128; i += 256){
      int row = i >> 7, k4 = i & 127;
      long hrow = ((long)(ssrc[row]+1)*BB + (b0 + row))*DD;
      HsV[row*128 + k4] = ((const float4*)(gS.H + hrow))[k4];
    }
    __syncthreads();

    u64 acc2[2][4];
    #pragma unroll
    for (int bi = 0; bi < 2; bi++)
      #pragma unroll
      for (int g = 0; g < 4; g++) acc2[bi][g] = 0ull;

    #pragma unroll 2
    for (int k4 = 0; k4 < 128; k4++){
      ulonglong2 h0 = HsV2[(bg*2+0)*128 + k4];
      ulonglong2 h1 = HsV2[(bg*2+1)*128 + k4];
      #pragma unroll
      for (int g = 0; g < 4; g++){
        ulonglong2 wv = WsV2[(long)(g*16 + n_local)*129 + k4];
        acc2[0][g] = ffma2(wv.x, h0.x, acc2[0][g]);
        acc2[0][g] = ffma2(wv.y, h0.y, acc2[0][g]);
        acc2[1][g] = ffma2(wv.x, h1.x, acc2[1][g]);
        acc2[1][g] = ffma2(wv.y, h1.y, acc2[1][g]);
      }
    }

    #pragma unroll
    for (int bi = 0; bi < 2; bi++){
      int bl = bg*2 + bi;
      int b = b0 + bl;
      int srcp = ssrc[bl] + 1;
      int n = n0 + n_local;
      const float* xp = gS.xproj + ((long)t*BB + b)*(4*DD);
      float gi = f2sum(acc2[bi][0]) + xp[n];
      float gf = f2sum(acc2[bi][1]) + xp[DD + n];
      float gg = f2sum(acc2[bi][2]) + xp[2*DD + n];
      float go = f2sum(acc2[bi][3]) + xp[3*DD + n];
      float cin = gS.C[((long)srcp*BB + b)*DD + n];
      float c = sigm(gf)*cin + sigm(gi)*tanhf(gg);
      float h = sigm(go)*tanhf(c);
      long o = ((long)(t+1)*BB + b)*DD + n;
      gS.H[o] = h;
      gS.C[o] = c;
    }
    if (t < TT-1) gbar_g(ctr, t, 32);
  }
}

// ---------------- prediction head -------------------------------------------
__global__ void head_kernel(const float* __restrict__ Wp, const float* __restrict__ bp,
                            float* __restrict__ out){
  int gw = (blockIdx.x*blockDim.x + threadIdx.x) >> 5;
  int lane = threadIdx.x & 31;
  if (gw >= BB*TT) return;
  int b = gw / TT, t = gw % TT;
  const float* h = gS.H + ((long)(t+1)*BB + b)*DD;
  float s = 0.f;
  for (int j = lane; j < DD; j += 32) s += h[j]*Wp[j];
  #pragma unroll
  for (int o = 16; o > 0; o >>= 1) s += __shfl_down_sync(0xffffffffu, s, o);
  if (lane == 0) out[b*TT + t] = sigm(s + bp[0]);
}

// ---------------- host orchestration ----------------------------------------
extern "C" void kernel_launch(void* const* d_in, const int* in_sizes, int n_in,
                              void* d_out, int out_size){
  (void)in_sizes; (void)n_in; (void)out_size;
  const int*   q     = (const int*)d_in[0];
  const int*   r     = (const int*)d_in[1];
  const float* Mk    = (const float*)d_in[2];
  const float* Mv0   = (const float*)d_in[3];
  const float* k_tab = (const float*)d_in[4];
  const float* x_tab = (const float*)d_in[5];
  const float* W_e   = (const float*)d_in[6];
  const float* b_e   = (const float*)d_in[7];
  const float* W_add = (const float*)d_in[8];
  const float* b_add = (const float*)d_in[9];
  const float* W_a   = (const float*)d_in[10];
  const float* b_a   = (const float*)d_in[11];
  const float* W_f   = (const float*)d_in[12];
  const float* b_f   = (const float*)d_in[13];
  const float* W_ih  = (const float*)d_in[14];
  const float* W_hh  = (const float*)d_in[15];
  const float* b_ih  = (const float*)d_in[16];
  const float* b_hh  = (const float*)d_in[17];
  const float* hx0   = (const float*)d_in[18];
  const float* cx0   = (const float*)d_in[19];
  const float* W_p   = (const float*)d_in[20];
  const float* b_p   = (const float*)d_in[21];
  float* out = (float*)d_out;

  Scratch* S = nullptr;
  cudaGetSymbolAddress((void**)&S, gS);

  cudaFuncSetAttribute(memrec_kernel, cudaFuncAttributeMaxDynamicSharedMemorySize, MEMREC_SMEM);
  cudaFuncSetAttribute(lstm_kernel,   cudaFuncAttributeMaxDynamicSharedMemorySize, LSTM_SMEM);

  const int ROWS = TT*BB; // 6144

  // ---- fused setup (inits + barrier reset + bias_ea + addressing) ----
  combo_kernel<<<NB_A + 128 + NC, 256>>>(q, r, hx0, cx0, b_ih, b_hh, W_a,
                                         W_e, W_add, b_a, b_e, b_add, Mk, k_tab);
  src_kernel<<<BB, 64>>>();

  // kproj_table = k_table @ W_f2^T + b_f        (2000 x 512)
  sgemm2_k<true><<<dim3(16,4), 256>>>(k_tab, NC, W_f + DD, 2*DD, b_f, S->kproj_t, DD);
  // Aea/Bea in one launch                        (2 x 1024 x 512)
  sgemm2_dual_k<<<dim3(8,8), 256>>>(S->Sw, S->WaT, S->Wa2T, S->Aea, S->Bea);
  // eaproj_table = x_table @ Bea^T + bias_ea    (4001 x 1024)
  sgemm2_k<true><<<dim3(32,8), 256>>>(x_tab, 2*NC+1, S->Bea, DD, S->bias_ea, S->eaproj_t, 2*DD);

  // ---- persistent memory recurrence ----
  memrec_kernel<<<128, 512, MEMREC_SMEM>>>(Mv0, W_f);

  // xproj = f @ W_ih^T + (b_ih + b_hh)          (6144 x 2048)
  sgemm2_k<true><<<dim3(48,16), 256>>>(S->f, ROWS, W_ih, DD, S->bihh, S->xproj, 4*DD);

  // ---- persistent hop-LSTM ----
  lstm_kernel<<<128, 256, LSTM_SMEM>>>(W_hh);

  // ---- head ----
  head_kernel<<<(BB*TT*32 + 255)/256, 256>>>(W_p, b_p, out);
}